// round 1
// baseline (speedup 1.0000x reference)
#include <cuda_runtime.h>
#include <math.h>

// Problem constants
#define Vv 50000
#define Ee 300
#define Hh 512
#define Ll 6
#define Nn 8192
#define Kk 4

// ---------------------------------------------------------------------------
// Scratch (device globals — no allocations allowed in kernel_launch)
// ---------------------------------------------------------------------------
__device__ float g_x[Nn * Ee];            // gathered+masked embeddings [N,E]
__device__ float g_xwiou[Nn * 3 * Hh];    // x @ W_iou                  [N,3H]
__device__ float g_xwf[Nn * Hh];          // x @ W_f                    [N,H]
__device__ float g_hk[Nn * Kk * Hh];      // masked child h             [N*K,H]
__device__ float g_fk[Nn * Kk * Hh];      // hk @ U_f                   [N*K,H]
__device__ float g_ht[Nn * Hh];           // child-sum h_tilde          [N,H]
__device__ float g_hu[Nn * 3 * Hh];       // h_tilde @ U_iou            [N,3H]
__device__ float g_hbuf[2 * Nn * Hh];     // ping-pong h
__device__ float g_cbuf[2 * Nn * Hh];     // ping-pong c

// ---------------------------------------------------------------------------
// Embedding gather: x[n,:] = embed[vocab_ix[n],:] * token_mask[n]
// Vectorized float4 over E (300 = 75 * 4)
// ---------------------------------------------------------------------------
__global__ void gather_x_kernel(const float* __restrict__ embed,
                                const int* __restrict__ vix,
                                const float* __restrict__ tmask,
                                float* __restrict__ x)
{
    int idx = blockIdx.x * blockDim.x + threadIdx.x;
    const int QE = Ee / 4;  // 75
    if (idx >= Nn * QE) return;
    int n = idx / QE;
    int q = idx - n * QE;
    float4 v = *(const float4*)(embed + (size_t)vix[n] * Ee + q * 4);
    float m = tmask[n];
    v.x *= m; v.y *= m; v.z *= m; v.w *= m;
    *(float4*)(x + (size_t)n * Ee + q * 4) = v;
}

// ---------------------------------------------------------------------------
// Child gather: hk[n,k,:] = h_prev[child_idx[n,k],:] * child_mask[n,k]
//               ht[n,:]   = sum_k hk[n,k,:]
// Vectorized float4 over H (512 = 128 * 4)
// ---------------------------------------------------------------------------
__global__ void gather_children_kernel(const int* __restrict__ cidx,
                                       const float* __restrict__ cmask,
                                       const float* __restrict__ h_prev,
                                       float* __restrict__ hk,
                                       float* __restrict__ ht)
{
    int idx = blockIdx.x * blockDim.x + threadIdx.x;
    const int QH = Hh / 4;  // 128
    if (idx >= Nn * QH) return;
    int n = idx / QH;
    int q = (idx - n * QH) * 4;
    float4 s = make_float4(0.f, 0.f, 0.f, 0.f);
#pragma unroll
    for (int k = 0; k < Kk; k++) {
        int ci = cidx[n * Kk + k];
        float m = cmask[n * Kk + k];
        float4 v = *(const float4*)(h_prev + (size_t)ci * Hh + q);
        v.x *= m; v.y *= m; v.z *= m; v.w *= m;
        *(float4*)(hk + (size_t)(n * Kk + k) * Hh + q) = v;
        s.x += v.x; s.y += v.y; s.z += v.z; s.w += v.w;
    }
    *(float4*)(ht + (size_t)n * Hh + q) = s;
}

// ---------------------------------------------------------------------------
// SGEMM: C[M,Ncol] = A[M,Kd] @ B[Kd,Ncol]   (row-major, optional bias add)
// 128x128 tile, BK=8, 256 threads, 8x8 microtile. M,Ncol multiples of 128.
// Kd multiple of 4 (300 or 512); K-remainder handled by zero-fill.
// ---------------------------------------------------------------------------
__global__ void __launch_bounds__(256)
sgemm_kernel(const float* __restrict__ A, const float* __restrict__ B,
             const float* __restrict__ bias, float* __restrict__ C,
             int M, int Kd, int Ncol)
{
    __shared__ float As[8 * 128];   // transposed: As[k][m]
    __shared__ float Bs[8 * 128];   // Bs[k][n]

    const int tid  = threadIdx.x;
    const int crow = blockIdx.y * 128;
    const int ccol = blockIdx.x * 128;

    // Global-load mapping (1 float4 per thread per tile)
    const int arow = tid >> 1;            // 0..127
    const int acol = (tid & 1) * 4;       // 0 or 4
    const int brow = tid >> 5;            // 0..7
    const int bcol = (tid & 31) * 4;      // 0..124

    // Compute mapping: 16x16 threads of 8x8
    const int trow = (tid >> 4) * 8;
    const int tcol = (tid & 15) * 8;

    float acc[8][8];
#pragma unroll
    for (int i = 0; i < 8; i++)
#pragma unroll
        for (int j = 0; j < 8; j++) acc[i][j] = 0.f;

    for (int k0 = 0; k0 < Kd; k0 += 8) {
        float4 av = make_float4(0.f, 0.f, 0.f, 0.f);
        if (k0 + acol < Kd)
            av = *(const float4*)(A + (size_t)(crow + arow) * Kd + k0 + acol);
        As[(acol + 0) * 128 + arow] = av.x;
        As[(acol + 1) * 128 + arow] = av.y;
        As[(acol + 2) * 128 + arow] = av.z;
        As[(acol + 3) * 128 + arow] = av.w;

        float4 bv = make_float4(0.f, 0.f, 0.f, 0.f);
        if (k0 + brow < Kd)
            bv = *(const float4*)(B + (size_t)(k0 + brow) * Ncol + ccol + bcol);
        *(float4*)(Bs + brow * 128 + bcol) = bv;

        __syncthreads();

#pragma unroll
        for (int k = 0; k < 8; k++) {
            float ar[8], br[8];
#pragma unroll
            for (int i = 0; i < 8; i++) ar[i] = As[k * 128 + trow + i];
#pragma unroll
            for (int j = 0; j < 8; j++) br[j] = Bs[k * 128 + tcol + j];
#pragma unroll
            for (int i = 0; i < 8; i++)
#pragma unroll
                for (int j = 0; j < 8; j++) acc[i][j] += ar[i] * br[j];
        }
        __syncthreads();
    }

    float breg[8];
#pragma unroll
    for (int j = 0; j < 8; j++)
        breg[j] = bias ? bias[ccol + tcol + j] : 0.f;

#pragma unroll
    for (int i = 0; i < 8; i++) {
        float* cp = C + (size_t)(crow + trow + i) * Ncol + ccol + tcol;
#pragma unroll
        for (int j = 0; j < 8; j += 4) {
            float4 v;
            v.x = acc[i][j + 0] + breg[j + 0];
            v.y = acc[i][j + 1] + breg[j + 1];
            v.z = acc[i][j + 2] + breg[j + 2];
            v.w = acc[i][j + 3] + breg[j + 3];
            *(float4*)(cp + j) = v;
        }
    }
}

// ---------------------------------------------------------------------------
// Node update (fused gates):
//   iou = xwiou + hu + b_iou ; f_k = sigmoid(xwf + fk + b_f)
//   fc  = sum_k f_k * c_prev[child_k] * mask_k
//   c   = sigmoid(i)*tanh(u) + fc ; h = sigmoid(o)*tanh(c)
// ---------------------------------------------------------------------------
__device__ __forceinline__ float sigmoidf_(float v)
{
    return 1.f / (1.f + __expf(-v));
}

template <bool LEAF>
__global__ void node_update_kernel(const float* __restrict__ xwiou,
                                   const float* __restrict__ hu,
                                   const float* __restrict__ xwf,
                                   const float* __restrict__ fk,
                                   const float* __restrict__ b_iou,
                                   const float* __restrict__ b_f,
                                   const int* __restrict__ cidx,
                                   const float* __restrict__ cmask,
                                   const float* __restrict__ c_prev,
                                   float* __restrict__ c_out,
                                   float* __restrict__ h_out)
{
    int idx = blockIdx.x * blockDim.x + threadIdx.x;
    if (idx >= Nn * Hh) return;
    int n = idx >> 9;           // / 512
    int j = idx & (Hh - 1);

    size_t base3 = (size_t)n * 3 * Hh;
    float gi = xwiou[base3 + j] + b_iou[j];
    float go = xwiou[base3 + Hh + j] + b_iou[Hh + j];
    float gu = xwiou[base3 + 2 * Hh + j] + b_iou[2 * Hh + j];

    float fc = 0.f;
    if (!LEAF) {
        gi += hu[base3 + j];
        go += hu[base3 + Hh + j];
        gu += hu[base3 + 2 * Hh + j];
        float xf = xwf[(size_t)n * Hh + j] + b_f[j];
#pragma unroll
        for (int k = 0; k < Kk; k++) {
            float f = sigmoidf_(xf + fk[(size_t)(n * Kk + k) * Hh + j]);
            int ci = cidx[n * Kk + k];
            float m = cmask[n * Kk + k];
            fc += f * c_prev[(size_t)ci * Hh + j] * m;
        }
    }

    float c = sigmoidf_(gi) * tanhf(gu) + fc;
    c_out[idx] = c;
    h_out[idx] = sigmoidf_(go) * tanhf(c);
}

// ---------------------------------------------------------------------------
// Launch
// ---------------------------------------------------------------------------
extern "C" void kernel_launch(void* const* d_in, const int* in_sizes, int n_in,
                              void* d_out, int out_size)
{
    const int*   vocab_ix   = (const int*)d_in[0];     // [L,N]
    const int*   child_idx  = (const int*)d_in[1];     // [L,N,K]
    const float* token_mask = (const float*)d_in[2];   // [L,N]
    const float* child_mask = (const float*)d_in[3];   // [L,N,K]
    const float* embed      = (const float*)d_in[4];   // [V,E]
    const float* W_iou      = (const float*)d_in[5];   // [E,3H]
    const float* U_iou      = (const float*)d_in[6];   // [H,3H]
    const float* b_iou      = (const float*)d_in[7];   // [3H]
    const float* W_f        = (const float*)d_in[8];   // [E,H]
    const float* U_f        = (const float*)d_in[9];   // [H,H]
    const float* b_f        = (const float*)d_in[10];  // [H]
    float* out = (float*)d_out;

    float *x, *xwiou, *xwf, *hk, *fk, *ht, *hu, *hbuf, *cbuf;
    cudaGetSymbolAddress((void**)&x,     g_x);
    cudaGetSymbolAddress((void**)&xwiou, g_xwiou);
    cudaGetSymbolAddress((void**)&xwf,   g_xwf);
    cudaGetSymbolAddress((void**)&hk,    g_hk);
    cudaGetSymbolAddress((void**)&fk,    g_fk);
    cudaGetSymbolAddress((void**)&ht,    g_ht);
    cudaGetSymbolAddress((void**)&hu,    g_hu);
    cudaGetSymbolAddress((void**)&hbuf,  g_hbuf);
    cudaGetSymbolAddress((void**)&cbuf,  g_cbuf);

    float* hp[2] = { hbuf, hbuf + (size_t)Nn * Hh };
    float* cp[2] = { cbuf, cbuf + (size_t)Nn * Hh };

    const int T = 256;
    const int gx_blocks = (Nn * (Ee / 4) + T - 1) / T;
    const int gc_blocks = (Nn * (Hh / 4) + T - 1) / T;
    const int nu_blocks = (Nn * Hh + T - 1) / T;

    int cur = 0;
    for (int l = Ll - 1; l >= 0; --l) {
        const bool leaf = (l == Ll - 1);
        const int prev = cur ^ 1;

        // x = embed[vocab_ix[l]] * token_mask[l]
        gather_x_kernel<<<gx_blocks, T>>>(embed, vocab_ix + l * Nn,
                                          token_mask + l * Nn, x);

        // xwiou = x @ W_iou   [N, 3H]
        sgemm_kernel<<<dim3(3 * Hh / 128, Nn / 128), 256>>>(
            x, W_iou, nullptr, xwiou, Nn, Ee, 3 * Hh);

        if (!leaf) {
            // xwf = x @ W_f   [N, H]
            sgemm_kernel<<<dim3(Hh / 128, Nn / 128), 256>>>(
                x, W_f, nullptr, xwf, Nn, Ee, Hh);

            // hk = masked child h gather, ht = child-sum
            gather_children_kernel<<<gc_blocks, T>>>(
                child_idx + l * Nn * Kk, child_mask + l * Nn * Kk,
                hp[prev], hk, ht);

            // fk = hk @ U_f   [N*K, H]
            sgemm_kernel<<<dim3(Hh / 128, (Nn * Kk) / 128), 256>>>(
                hk, U_f, nullptr, fk, Nn * Kk, Hh, Hh);

            // hu = ht @ U_iou [N, 3H]
            sgemm_kernel<<<dim3(3 * Hh / 128, Nn / 128), 256>>>(
                ht, U_iou, nullptr, hu, Nn, Hh, 3 * Hh);
        }

        float* hout = (l == 0) ? out : hp[cur];
        if (leaf) {
            node_update_kernel<true><<<nu_blocks, T>>>(
                xwiou, nullptr, nullptr, nullptr, b_iou, b_f,
                nullptr, nullptr, nullptr, cp[cur], hout);
        } else {
            node_update_kernel<false><<<nu_blocks, T>>>(
                xwiou, hu, xwf, fk, b_iou, b_f,
                child_idx + l * Nn * Kk, child_mask + l * Nn * Kk,
                cp[prev], cp[cur], hout);
        }
        cur ^= 1;
    }
}

// round 3
// speedup vs baseline: 3.7612x; 3.7612x over previous
#include <cuda_runtime.h>
#include <cuda_bf16.h>
#include <math.h>
#include <stdint.h>

// Problem constants
#define Vv 50000
#define Ee 300
#define EPAD 320
#define Hh 512
#define Ll 6
#define Nn 8192
#define Kk 4

// ---------------------------------------------------------------------------
// Feature gate: tcgen05 exists only on arch-accelerated / family-specific
// device passes (sm_103a / sm_103f). The plain compute_103 PTX pass gets a
// baseline mma.sync fallback so ptxas never sees tcgen05 on a non-'a' target.
// ---------------------------------------------------------------------------
#if defined(__CUDA_ARCH__) && (defined(__CUDA_ARCH_FEAT_SM103_ALL) || \
    defined(__CUDA_ARCH_FEAT_SM100_ALL) || defined(__CUDA_ARCH_FEAT_SM110_ALL) || \
    (defined(__CUDA_ARCH_FAMILY_SPECIFIC__) && (__CUDA_ARCH_FAMILY_SPECIFIC__ >= 1000)))
#define USE_TCGEN05 1
#else
#define USE_TCGEN05 0
#endif

// ---------------------------------------------------------------------------
// Scratch (device globals — no allocations allowed)
// ---------------------------------------------------------------------------
__device__ __nv_bfloat16 g_xhi[Nn * EPAD];
__device__ __nv_bfloat16 g_xlo[Nn * EPAD];
__device__ __nv_bfloat16 g_hkhi[Nn * Kk * Hh];
__device__ __nv_bfloat16 g_hklo[Nn * Kk * Hh];
__device__ __nv_bfloat16 g_hthi[Nn * Hh];
__device__ __nv_bfloat16 g_htlo[Nn * Hh];

__device__ __nv_bfloat16 g_WiouT_hi[3 * Hh * EPAD];
__device__ __nv_bfloat16 g_WiouT_lo[3 * Hh * EPAD];
__device__ __nv_bfloat16 g_WfT_hi[Hh * EPAD];
__device__ __nv_bfloat16 g_WfT_lo[Hh * EPAD];
__device__ __nv_bfloat16 g_UiouT_hi[3 * Hh * Hh];
__device__ __nv_bfloat16 g_UiouT_lo[3 * Hh * Hh];
__device__ __nv_bfloat16 g_UfT_hi[Hh * Hh];
__device__ __nv_bfloat16 g_UfT_lo[Hh * Hh];

__device__ float g_xwiou[Nn * 3 * Hh];
__device__ float g_xwf[Nn * Hh];
__device__ float g_fk[Nn * Kk * Hh];
__device__ float g_hu[Nn * 3 * Hh];
__device__ float g_hbuf[2 * Nn * Hh];
__device__ float g_cbuf[2 * Nn * Hh];

// ---------------------------------------------------------------------------
// Common PTX helpers (baseline ISA, legal on all passes)
// ---------------------------------------------------------------------------
__device__ __forceinline__ uint32_t smem_u32(const void* p) {
    uint32_t a;
    asm("{ .reg .u64 t; cvta.to.shared.u64 t, %1; cvt.u32.u64 %0, t; }"
        : "=r"(a) : "l"(p));
    return a;
}

__device__ __forceinline__ void cp16(uint32_t dst, const void* src) {
    asm volatile("cp.async.cg.shared.global [%0], [%1], 16;"
                 :: "r"(dst), "l"(src));
}

#define CP_COMMIT()  asm volatile("cp.async.commit_group;" ::: "memory")
#define CP_WAIT0()   asm volatile("cp.async.wait_group 0;" ::: "memory")
#define CP_WAIT1()   asm volatile("cp.async.wait_group 1;" ::: "memory")
#define FENCE_ASYNC() asm volatile("fence.proxy.async.shared::cta;" ::: "memory")
#define MBAR_INIT(a, cnt) \
    asm volatile("mbarrier.init.shared.b64 [%0], %1;" :: "r"(a), "r"(cnt) : "memory")

// SW128 swizzle + smem descriptor (layout 2 = SW128, version 1, SBO=64, LBO=1)
#define SW128u(o) ((uint32_t)(o) ^ ((((uint32_t)(o)) >> 3) & 0x70u))
#define DESC_BASE ((2ull << 61) | (1ull << 46) | (64ull << 32) | (1ull << 16))
#define MAKE_DESC(a) (DESC_BASE | (((uint64_t)((a) >> 4)) & 0x3FFFull))
// idesc: fp32 accum, bf16 A/B, K-major, M=128, N=128
#define IDESC_128 (0x10u | 0x80u | 0x400u | (16u << 17) | (8u << 24))

#if USE_TCGEN05
// ---------------------------------------------------------------------------
// tcgen05 helpers (only compiled on the arch-accelerated pass)
// ---------------------------------------------------------------------------
__device__ __forceinline__ uint32_t elect1() {
    uint32_t p;
    asm volatile("{ .reg .pred p; elect.sync _|p, 0xFFFFFFFF; selp.b32 %0,1,0,p; }"
                 : "=r"(p));
    return p;
}

__device__ __forceinline__ void mbar_wait(uint32_t mbar, uint32_t parity) {
    asm volatile(
        "{\n\t.reg .pred P;\n\t"
        "WL_%=:\n\t"
        "mbarrier.try_wait.parity.acquire.cta.shared::cta.b64 P, [%0], %1, 0x989680;\n\t"
        "@P bra.uni WD_%=;\n\t"
        "bra.uni WL_%=;\n\t"
        "WD_%=:\n\t}"
        :: "r"(mbar), "r"(parity) : "memory");
}

#define TC_ALLOC(a, n) \
    asm volatile("tcgen05.alloc.cta_group::1.sync.aligned.shared::cta.b32 [%0], %1;" \
                 :: "r"(a), "r"(n) : "memory")
#define TC_DEALLOC(t, n) \
    asm volatile("tcgen05.dealloc.cta_group::1.sync.aligned.b32 %0, %1;" :: "r"(t), "r"(n))
#define TC_RELINQ() \
    asm volatile("tcgen05.relinquish_alloc_permit.cta_group::1.sync.aligned;")
#define TC_COMMIT(m) \
    asm volatile("tcgen05.commit.cta_group::1.mbarrier::arrive::one.shared::cluster.b64 [%0];" \
                 :: "r"(m) : "memory")
#define TC_FENCE_AFTER()  asm volatile("tcgen05.fence::after_thread_sync;" ::: "memory")
#define TC_FENCE_BEFORE() asm volatile("tcgen05.fence::before_thread_sync;" ::: "memory")
#define TC_WAIT_LD()      asm volatile("tcgen05.wait::ld.sync.aligned;" ::: "memory")

__device__ __forceinline__ void mma_bf16_ss(uint32_t d, uint64_t ad, uint64_t bd,
                                            uint32_t idesc, uint32_t en) {
    asm volatile(
        "{\n\t.reg .pred p;\n\t"
        "setp.ne.u32 p, %4, 0;\n\t"
        "tcgen05.mma.cta_group::1.kind::f16 [%0], %1, %2, %3, {%5,%5,%5,%5}, p;\n\t}"
        :: "r"(d), "l"(ad), "l"(bd), "r"(idesc), "r"(en), "r"(0u) : "memory");
}

__device__ __forceinline__ void ldtm32(uint32_t* r, uint32_t taddr) {
    asm volatile(
        "tcgen05.ld.sync.aligned.32x32b.x32.b32 "
        "{%0, %1, %2, %3, %4, %5, %6, %7, %8, %9, %10, %11, %12, %13, %14, %15, "
        "%16, %17, %18, %19, %20, %21, %22, %23, %24, %25, %26, %27, %28, %29, %30, %31}, [%32];"
        : "=r"(r[0]), "=r"(r[1]), "=r"(r[2]), "=r"(r[3]), "=r"(r[4]), "=r"(r[5]),
          "=r"(r[6]), "=r"(r[7]), "=r"(r[8]), "=r"(r[9]), "=r"(r[10]), "=r"(r[11]),
          "=r"(r[12]), "=r"(r[13]), "=r"(r[14]), "=r"(r[15]), "=r"(r[16]), "=r"(r[17]),
          "=r"(r[18]), "=r"(r[19]), "=r"(r[20]), "=r"(r[21]), "=r"(r[22]), "=r"(r[23]),
          "=r"(r[24]), "=r"(r[25]), "=r"(r[26]), "=r"(r[27]), "=r"(r[28]), "=r"(r[29]),
          "=r"(r[30]), "=r"(r[31])
        : "r"(taddr));
}
#endif  // USE_TCGEN05

// ---------------------------------------------------------------------------
// Baseline-ISA warp MMA (m16n8k16 bf16) — used by the fallback body
// ---------------------------------------------------------------------------
__device__ __forceinline__ void hmma16816(float* d, const uint32_t* a, const uint32_t* b) {
    asm volatile(
        "mma.sync.aligned.m16n8k16.row.col.f32.bf16.bf16.f32 "
        "{%0,%1,%2,%3}, {%4,%5,%6,%7}, {%8,%9}, {%0,%1,%2,%3};"
        : "+f"(d[0]), "+f"(d[1]), "+f"(d[2]), "+f"(d[3])
        : "r"(a[0]), "r"(a[1]), "r"(a[2]), "r"(a[3]), "r"(b[0]), "r"(b[1]));
}

// ---------------------------------------------------------------------------
// Split helper
// ---------------------------------------------------------------------------
__device__ __forceinline__ void split_bf16(float v, __nv_bfloat16& hi, __nv_bfloat16& lo) {
    hi = __float2bfloat16(v);
    lo = __float2bfloat16(v - __bfloat162float(hi));
}

// ---------------------------------------------------------------------------
// Weight prep: T[n][k] = W[k][n] (k < Korig else 0), split hi/lo.
// ---------------------------------------------------------------------------
__global__ void prep_weight_kernel(const float* __restrict__ W,
                                   __nv_bfloat16* __restrict__ Thi,
                                   __nv_bfloat16* __restrict__ Tlo,
                                   int Korig, int Kpad, int Ncol)
{
    int idx = blockIdx.x * blockDim.x + threadIdx.x;
    if (idx >= Ncol * Kpad) return;
    int n = idx / Kpad;
    int k = idx - n * Kpad;
    float v = (k < Korig) ? W[(size_t)k * Ncol + n] : 0.f;
    __nv_bfloat16 hi, lo;
    split_bf16(v, hi, lo);
    Thi[idx] = hi;
    Tlo[idx] = lo;
}

// ---------------------------------------------------------------------------
// Embedding gather + split
// ---------------------------------------------------------------------------
__global__ void gather_x_kernel(const float* __restrict__ embed,
                                const int* __restrict__ vix,
                                const float* __restrict__ tmask,
                                __nv_bfloat16* __restrict__ xhi,
                                __nv_bfloat16* __restrict__ xlo)
{
    int idx = blockIdx.x * blockDim.x + threadIdx.x;
    const int QE = EPAD / 2;  // 160
    if (idx >= Nn * QE) return;
    int n = idx / QE;
    int e = (idx - n * QE) * 2;
    float m = tmask[n];
    float v0 = 0.f, v1 = 0.f;
    if (e < Ee) {
        const float* er = embed + (size_t)vix[n] * Ee + e;
        v0 = er[0] * m;
        v1 = er[1] * m;
    }
    __nv_bfloat16 h0, l0, h1, l1;
    split_bf16(v0, h0, l0);
    split_bf16(v1, h1, l1);
    *(__nv_bfloat162*)(xhi + (size_t)n * EPAD + e) = __nv_bfloat162(h0, h1);
    *(__nv_bfloat162*)(xlo + (size_t)n * EPAD + e) = __nv_bfloat162(l0, l1);
}

// ---------------------------------------------------------------------------
// Child gather + split
// ---------------------------------------------------------------------------
__global__ void gather_children_kernel(const int* __restrict__ cidx,
                                       const float* __restrict__ cmask,
                                       const float* __restrict__ h_prev,
                                       __nv_bfloat16* __restrict__ hkhi,
                                       __nv_bfloat16* __restrict__ hklo,
                                       __nv_bfloat16* __restrict__ hthi,
                                       __nv_bfloat16* __restrict__ htlo)
{
    int idx = blockIdx.x * blockDim.x + threadIdx.x;
    const int QH = Hh / 2;  // 256
    if (idx >= Nn * QH) return;
    int n = idx / QH;
    int q = (idx - n * QH) * 2;
    float s0 = 0.f, s1 = 0.f;
#pragma unroll
    for (int k = 0; k < Kk; k++) {
        int ci = cidx[n * Kk + k];
        float m = cmask[n * Kk + k];
        float2 v = *(const float2*)(h_prev + (size_t)ci * Hh + q);
        v.x *= m; v.y *= m;
        __nv_bfloat16 h0, l0, h1, l1;
        split_bf16(v.x, h0, l0);
        split_bf16(v.y, h1, l1);
        size_t o = (size_t)(n * Kk + k) * Hh + q;
        *(__nv_bfloat162*)(hkhi + o) = __nv_bfloat162(h0, h1);
        *(__nv_bfloat162*)(hklo + o) = __nv_bfloat162(l0, l1);
        s0 += v.x; s1 += v.y;
    }
    __nv_bfloat16 h0, l0, h1, l1;
    split_bf16(s0, h0, l0);
    split_bf16(s1, h1, l1);
    *(__nv_bfloat162*)(hthi + (size_t)n * Hh + q) = __nv_bfloat162(h0, h1);
    *(__nv_bfloat162*)(htlo + (size_t)n * Hh + q) = __nv_bfloat162(l0, l1);
}

// ---------------------------------------------------------------------------
// Split-bf16 GEMM: C[M,Ncol] = (Ahi+Alo)[M,Ks] @ (Bhi+Blo)[Ncol,Ks]^T
// 128x128 tile per CTA, 256 threads.
// Body 1 (sm_103a pass): tcgen05 + TMEM, K-chunks of 64, cp.async dbl-buffer.
// Body 2 (plain pass):   mma.sync m16n8k16, K-chunks of 32, cp.async dbl-buffer.
// ---------------------------------------------------------------------------
__global__ void __launch_bounds__(256)
gemm_split_kernel(const __nv_bfloat16* __restrict__ Ahi,
                  const __nv_bfloat16* __restrict__ Alo,
                  const __nv_bfloat16* __restrict__ Bhi,
                  const __nv_bfloat16* __restrict__ Blo,
                  float* __restrict__ C,
                  int M, int Ks, int Ncol)
{
#if USE_TCGEN05
    extern __shared__ char smem_raw[];
    const uint32_t sb = smem_u32(smem_raw);
    const uint32_t ctrl = sb;                               // tmem ptr @0, mbar @8,@16
    const uint32_t tiles = (sb + 64 + 1023) & ~1023u;       // 1024-aligned tile base

    const int tid = threadIdx.x;
    const int wid = tid >> 5;
    const int lid = tid & 31;
    const int m0 = blockIdx.y * 128;
    const int n0 = blockIdx.x * 128;
    const int NC = Ks >> 6;

    if (wid == 0) TC_ALLOC(ctrl, 128);
    if (tid == 0) { MBAR_INIT(ctrl + 8, 1); MBAR_INIT(ctrl + 16, 1); }
    __syncthreads();
    uint32_t tmem;
    asm("ld.shared.b32 %0, [%1];" : "=r"(tmem) : "r"(ctrl));

    // Tile buffer layout: buf*65536 + {Ahi:0, Alo:16K, Bhi:32K, Blo:48K}
    auto load_chunk = [&](int buf, int k0) {
        uint32_t tb = tiles + buf * 65536;
#pragma unroll
        for (int q = tid; q < 1024; q += 256) {
            int row = q >> 3;
            int c = q & 7;
            uint32_t soff = SW128u(row * 128 + c * 16);
            size_t ao = (size_t)(m0 + row) * Ks + k0 + c * 8;
            size_t bo = (size_t)(n0 + row) * Ks + k0 + c * 8;
            cp16(tb + soff,         Ahi + ao);
            cp16(tb + 16384 + soff, Alo + ao);
            cp16(tb + 32768 + soff, Bhi + bo);
            cp16(tb + 49152 + soff, Blo + bo);
        }
        CP_COMMIT();
    };

    uint32_t ph0 = 0, ph1 = 0;
    load_chunk(0, 0);

    for (int c = 0; c < NC; c++) {
        const int cur = c & 1;
        const int nxt = cur ^ 1;

        CP_WAIT0();
        FENCE_ASYNC();
        __syncthreads();

        if (c >= 1) {
            uint32_t mb = ctrl + 8 + nxt * 8;
            uint32_t ph = nxt ? ph1 : ph0;
            mbar_wait(mb, ph);
            if (nxt) ph1 ^= 1; else ph0 ^= 1;
        }
        if (c + 1 < NC) load_chunk(nxt, (c + 1) * 64);

        if (wid == 0 && elect1()) {
            uint32_t tb = tiles + cur * 65536;
            uint64_t dah = MAKE_DESC(tb);
            uint64_t dal = MAKE_DESC(tb + 16384);
            uint64_t dbh = MAKE_DESC(tb + 32768);
            uint64_t dbl = MAKE_DESC(tb + 49152);
#pragma unroll
            for (int ks = 0; ks < 4; ks++)
                mma_bf16_ss(tmem, dah + 2 * ks, dbh + 2 * ks, IDESC_128,
                            (c == 0 && ks == 0) ? 0u : 1u);
#pragma unroll
            for (int ks = 0; ks < 4; ks++)
                mma_bf16_ss(tmem, dah + 2 * ks, dbl + 2 * ks, IDESC_128, 1u);
#pragma unroll
            for (int ks = 0; ks < 4; ks++)
                mma_bf16_ss(tmem, dal + 2 * ks, dbh + 2 * ks, IDESC_128, 1u);
            TC_COMMIT(ctrl + 8 + cur * 8);
        }
    }

    {
        const int last = (NC - 1) & 1;
        uint32_t ph = last ? ph1 : ph0;
        mbar_wait(ctrl + 8 + last * 8, ph);
    }
    TC_FENCE_AFTER();

    if (wid < 4) {
        float* crow = C + (size_t)(m0 + wid * 32 + lid) * Ncol + n0;
#pragma unroll
        for (int b = 0; b < 4; b++) {
            uint32_t r[32];
            ldtm32(r, tmem + b * 32);
            TC_WAIT_LD();
#pragma unroll
            for (int j = 0; j < 32; j += 4) {
                float4 v;
                v.x = __uint_as_float(r[j + 0]);
                v.y = __uint_as_float(r[j + 1]);
                v.z = __uint_as_float(r[j + 2]);
                v.w = __uint_as_float(r[j + 3]);
                *(float4*)(crow + b * 32 + j) = v;
            }
        }
        TC_FENCE_BEFORE();
    }

    __syncthreads();
    if (wid == 0) {
        TC_RELINQ();
        TC_DEALLOC(tmem, 128);
    }

#else  // ------------------------- mma.sync fallback -------------------------
    extern __shared__ char smem_raw[];
    // buf*40960 + {Ahi:0, Alo:10240, Bhi:20480, Blo:30720}; 80B row stride
    const int tid = threadIdx.x;
    const int wid = tid >> 5;
    const int lane = tid & 31;
    const int wm = wid >> 1;       // 0..3  (M warps)
    const int wn = wid & 1;        // 0..1  (N warps)
    const int r4 = lane >> 2;
    const int tig = lane & 3;
    const int m0 = blockIdx.y * 128;
    const int n0 = blockIdx.x * 128;
    const int NC = Ks >> 5;

    float acc[2][8][4];
#pragma unroll
    for (int i = 0; i < 2; i++)
#pragma unroll
        for (int j = 0; j < 8; j++)
#pragma unroll
            for (int v = 0; v < 4; v++) acc[i][j][v] = 0.f;

    auto ldtile = [&](int buf, int k0) {
        uint32_t tb = smem_u32(smem_raw) + buf * 40960;
#pragma unroll
        for (int q = tid; q < 512; q += 256) {
            int row = q >> 2;
            int c = q & 3;
            uint32_t d = tb + row * 80 + c * 16;
            size_t ao = (size_t)(m0 + row) * Ks + k0 + c * 8;
            size_t bo = (size_t)(n0 + row) * Ks + k0 + c * 8;
            cp16(d,         Ahi + ao);
            cp16(d + 10240, Alo + ao);
            cp16(d + 20480, Bhi + bo);
            cp16(d + 30720, Blo + bo);
        }
        CP_COMMIT();
    };

    ldtile(0, 0);

    for (int c = 0; c < NC; c++) {
        const int cur = c & 1;
        if (c + 1 < NC) {
            ldtile(cur ^ 1, (c + 1) * 32);
            CP_WAIT1();
        } else {
            CP_WAIT0();
        }
        __syncthreads();

        const char* tb = smem_raw + cur * 40960;
#pragma unroll
        for (int kk = 0; kk < 32; kk += 16) {
            uint32_t ahi[2][4], alo[2][4], bhi[8][2], blo[8][2];
#pragma unroll
            for (int mi = 0; mi < 2; mi++) {
                int row = wm * 32 + mi * 16 + r4;
                int cb = (kk + tig * 2) * 2;
                ahi[mi][0] = *(const uint32_t*)(tb + row * 80 + cb);
                ahi[mi][1] = *(const uint32_t*)(tb + (row + 8) * 80 + cb);
                ahi[mi][2] = *(const uint32_t*)(tb + row * 80 + cb + 16);
                ahi[mi][3] = *(const uint32_t*)(tb + (row + 8) * 80 + cb + 16);
                alo[mi][0] = *(const uint32_t*)(tb + 10240 + row * 80 + cb);
                alo[mi][1] = *(const uint32_t*)(tb + 10240 + (row + 8) * 80 + cb);
                alo[mi][2] = *(const uint32_t*)(tb + 10240 + row * 80 + cb + 16);
                alo[mi][3] = *(const uint32_t*)(tb + 10240 + (row + 8) * 80 + cb + 16);
            }
#pragma unroll
            for (int ni = 0; ni < 8; ni++) {
                int nr = wn * 64 + ni * 8 + r4;
                int cb = (kk + tig * 2) * 2;
                bhi[ni][0] = *(const uint32_t*)(tb + 20480 + nr * 80 + cb);
                bhi[ni][1] = *(const uint32_t*)(tb + 20480 + nr * 80 + cb + 16);
                blo[ni][0] = *(const uint32_t*)(tb + 30720 + nr * 80 + cb);
                blo[ni][1] = *(const uint32_t*)(tb + 30720 + nr * 80 + cb + 16);
            }
#pragma unroll
            for (int mi = 0; mi < 2; mi++)
#pragma unroll
                for (int ni = 0; ni < 8; ni++) {
                    hmma16816(acc[mi][ni], ahi[mi], bhi[ni]);
                    hmma16816(acc[mi][ni], ahi[mi], blo[ni]);
                    hmma16816(acc[mi][ni], alo[mi], bhi[ni]);
                }
        }
        __syncthreads();
    }

#pragma unroll
    for (int mi = 0; mi < 2; mi++)
#pragma unroll
        for (int ni = 0; ni < 8; ni++) {
            int row = m0 + wm * 32 + mi * 16 + r4;
            int col = n0 + wn * 64 + ni * 8 + tig * 2;
            *(float2*)(C + (size_t)row * Ncol + col) =
                make_float2(acc[mi][ni][0], acc[mi][ni][1]);
            *(float2*)(C + (size_t)(row + 8) * Ncol + col) =
                make_float2(acc[mi][ni][2], acc[mi][ni][3]);
        }
#endif
}

// ---------------------------------------------------------------------------
// Node update (fused gates)
// ---------------------------------------------------------------------------
__device__ __forceinline__ float sigmoidf_(float v) {
    return 1.f / (1.f + __expf(-v));
}

template <bool LEAF>
__global__ void node_update_kernel(const float* __restrict__ xwiou,
                                   const float* __restrict__ hu,
                                   const float* __restrict__ xwf,
                                   const float* __restrict__ fk,
                                   const float* __restrict__ b_iou,
                                   const float* __restrict__ b_f,
                                   const int* __restrict__ cidx,
                                   const float* __restrict__ cmask,
                                   const float* __restrict__ c_prev,
                                   float* __restrict__ c_out,
                                   float* __restrict__ h_out)
{
    int idx = blockIdx.x * blockDim.x + threadIdx.x;
    if (idx >= Nn * Hh) return;
    int n = idx >> 9;
    int j = idx & (Hh - 1);

    size_t base3 = (size_t)n * 3 * Hh;
    float gi = xwiou[base3 + j] + b_iou[j];
    float go = xwiou[base3 + Hh + j] + b_iou[Hh + j];
    float gu = xwiou[base3 + 2 * Hh + j] + b_iou[2 * Hh + j];

    float fc = 0.f;
    if (!LEAF) {
        gi += hu[base3 + j];
        go += hu[base3 + Hh + j];
        gu += hu[base3 + 2 * Hh + j];
        float xf = xwf[(size_t)n * Hh + j] + b_f[j];
#pragma unroll
        for (int k = 0; k < Kk; k++) {
            float f = sigmoidf_(xf + fk[(size_t)(n * Kk + k) * Hh + j]);
            int ci = cidx[n * Kk + k];
            float m = cmask[n * Kk + k];
            fc += f * c_prev[(size_t)ci * Hh + j] * m;
        }
    }

    float c = sigmoidf_(gi) * tanhf(gu) + fc;
    c_out[idx] = c;
    h_out[idx] = sigmoidf_(go) * tanhf(c);
}

// ---------------------------------------------------------------------------
// Launch
// ---------------------------------------------------------------------------
extern "C" void kernel_launch(void* const* d_in, const int* in_sizes, int n_in,
                              void* d_out, int out_size)
{
    const int*   vocab_ix   = (const int*)d_in[0];
    const int*   child_idx  = (const int*)d_in[1];
    const float* token_mask = (const float*)d_in[2];
    const float* child_mask = (const float*)d_in[3];
    const float* embed      = (const float*)d_in[4];
    const float* W_iou      = (const float*)d_in[5];   // [E, 3H]
    const float* U_iou      = (const float*)d_in[6];   // [H, 3H]
    const float* b_iou      = (const float*)d_in[7];
    const float* W_f        = (const float*)d_in[8];   // [E, H]
    const float* U_f        = (const float*)d_in[9];   // [H, H]
    const float* b_f        = (const float*)d_in[10];
    float* out = (float*)d_out;

    static const int GEMM_SMEM = 133120;
    cudaFuncSetAttribute(gemm_split_kernel,
                         cudaFuncAttributeMaxDynamicSharedMemorySize, GEMM_SMEM);

    __nv_bfloat16 *xhi, *xlo, *hkhi, *hklo, *hthi, *htlo;
    __nv_bfloat16 *WiouThi, *WiouTlo, *WfThi, *WfTlo, *UiouThi, *UiouTlo, *UfThi, *UfTlo;
    float *xwiou, *xwf, *fk, *hu, *hbuf, *cbuf;
    cudaGetSymbolAddress((void**)&xhi, g_xhi);
    cudaGetSymbolAddress((void**)&xlo, g_xlo);
    cudaGetSymbolAddress((void**)&hkhi, g_hkhi);
    cudaGetSymbolAddress((void**)&hklo, g_hklo);
    cudaGetSymbolAddress((void**)&hthi, g_hthi);
    cudaGetSymbolAddress((void**)&htlo, g_htlo);
    cudaGetSymbolAddress((void**)&WiouThi, g_WiouT_hi);
    cudaGetSymbolAddress((void**)&WiouTlo, g_WiouT_lo);
    cudaGetSymbolAddress((void**)&WfThi, g_WfT_hi);
    cudaGetSymbolAddress((void**)&WfTlo, g_WfT_lo);
    cudaGetSymbolAddress((void**)&UiouThi, g_UiouT_hi);
    cudaGetSymbolAddress((void**)&UiouTlo, g_UiouT_lo);
    cudaGetSymbolAddress((void**)&UfThi, g_UfT_hi);
    cudaGetSymbolAddress((void**)&UfTlo, g_UfT_lo);
    cudaGetSymbolAddress((void**)&xwiou, g_xwiou);
    cudaGetSymbolAddress((void**)&xwf, g_xwf);
    cudaGetSymbolAddress((void**)&fk, g_fk);
    cudaGetSymbolAddress((void**)&hu, g_hu);
    cudaGetSymbolAddress((void**)&hbuf, g_hbuf);
    cudaGetSymbolAddress((void**)&cbuf, g_cbuf);

    float* hp[2] = { hbuf, hbuf + (size_t)Nn * Hh };
    float* cp[2] = { cbuf, cbuf + (size_t)Nn * Hh };

    const int T = 256;

    // Weight prep (constant across levels)
    prep_weight_kernel<<<(3 * Hh * EPAD + T - 1) / T, T>>>(W_iou, WiouThi, WiouTlo, Ee, EPAD, 3 * Hh);
    prep_weight_kernel<<<(Hh * EPAD + T - 1) / T, T>>>(W_f, WfThi, WfTlo, Ee, EPAD, Hh);
    prep_weight_kernel<<<(3 * Hh * Hh + T - 1) / T, T>>>(U_iou, UiouThi, UiouTlo, Hh, Hh, 3 * Hh);
    prep_weight_kernel<<<(Hh * Hh + T - 1) / T, T>>>(U_f, UfThi, UfTlo, Hh, Hh, Hh);

    const int gx_blocks = (Nn * (EPAD / 2) + T - 1) / T;
    const int gc_blocks = (Nn * (Hh / 2) + T - 1) / T;
    const int nu_blocks = (Nn * Hh + T - 1) / T;

    int cur = 0;
    for (int l = Ll - 1; l >= 0; --l) {
        const bool leaf = (l == Ll - 1);
        const int prev = cur ^ 1;

        gather_x_kernel<<<gx_blocks, T>>>(embed, vocab_ix + l * Nn,
                                          token_mask + l * Nn, xhi, xlo);

        gemm_split_kernel<<<dim3(3 * Hh / 128, Nn / 128), 256, GEMM_SMEM>>>(
            xhi, xlo, WiouThi, WiouTlo, xwiou, Nn, EPAD, 3 * Hh);

        if (!leaf) {
            gemm_split_kernel<<<dim3(Hh / 128, Nn / 128), 256, GEMM_SMEM>>>(
                xhi, xlo, WfThi, WfTlo, xwf, Nn, EPAD, Hh);

            gather_children_kernel<<<gc_blocks, T>>>(
                child_idx + l * Nn * Kk, child_mask + l * Nn * Kk,
                hp[prev], hkhi, hklo, hthi, htlo);

            gemm_split_kernel<<<dim3(Hh / 128, (Nn * Kk) / 128), 256, GEMM_SMEM>>>(
                hkhi, hklo, UfThi, UfTlo, fk, Nn * Kk, Hh, Hh);

            gemm_split_kernel<<<dim3(3 * Hh / 128, Nn / 128), 256, GEMM_SMEM>>>(
                hthi, htlo, UiouThi, UiouTlo, hu, Nn, Hh, 3 * Hh);
        }

        float* hout = (l == 0) ? out : hp[cur];
        if (leaf) {
            node_update_kernel<true><<<nu_blocks, T>>>(
                xwiou, nullptr, nullptr, nullptr, b_iou, b_f,
                nullptr, nullptr, nullptr, cp[cur], hout);
        } else {
            node_update_kernel<false><<<nu_blocks, T>>>(
                xwiou, hu, xwf, fk, b_iou, b_f,
                child_idx + l * Nn * Kk, child_mask + l * Nn * Kk,
                cp[prev], cp[cur], hout);
        }
        cur ^= 1;
    }
}

// round 4
// speedup vs baseline: 5.9186x; 1.5736x over previous
#include <cuda_runtime.h>
#include <cuda_bf16.h>
#include <math.h>
#include <stdint.h>

// Problem constants
#define Vv 50000
#define Ee 300
#define EPAD 320
#define Hh 512
#define Ll 6
#define Nn 8192
#define Kk 4
#define NCAT 2048   // [iou (1536) | f (512)] concatenated output columns

// ---------------------------------------------------------------------------
// Feature gate: tcgen05 exists only on arch-accelerated / family passes.
// ---------------------------------------------------------------------------
#if defined(__CUDA_ARCH__) && (defined(__CUDA_ARCH_FEAT_SM103_ALL) || \
    defined(__CUDA_ARCH_FEAT_SM100_ALL) || defined(__CUDA_ARCH_FEAT_SM110_ALL) || \
    (defined(__CUDA_ARCH_FAMILY_SPECIFIC__) && (__CUDA_ARCH_FAMILY_SPECIFIC__ >= 1000)))
#define USE_TCGEN05 1
#else
#define USE_TCGEN05 0
#endif

// ---------------------------------------------------------------------------
// Scratch
// ---------------------------------------------------------------------------
__device__ __nv_bfloat16 g_xhi[Nn * EPAD];
__device__ __nv_bfloat16 g_xlo[Nn * EPAD];
__device__ __nv_bfloat16 g_hhi[Nn * Hh];
__device__ __nv_bfloat16 g_hlo[Nn * Hh];

__device__ __nv_bfloat16 g_WcatT_hi[NCAT * EPAD];
__device__ __nv_bfloat16 g_WcatT_lo[NCAT * EPAD];
__device__ __nv_bfloat16 g_UcatT_hi[NCAT * Hh];
__device__ __nv_bfloat16 g_UcatT_lo[NCAT * Hh];

__device__ float g_xw4[Nn * NCAT];   // x @ [W_iou|W_f]
__device__ float g_hu4[Nn * NCAT];   // h @ [U_iou|U_f]
__device__ float g_cbuf[2 * Nn * Hh];

// ---------------------------------------------------------------------------
// Common PTX helpers
// ---------------------------------------------------------------------------
__device__ __forceinline__ uint32_t smem_u32(const void* p) {
    uint32_t a;
    asm("{ .reg .u64 t; cvta.to.shared.u64 t, %1; cvt.u32.u64 %0, t; }"
        : "=r"(a) : "l"(p));
    return a;
}

__device__ __forceinline__ void cp16(uint32_t dst, const void* src) {
    asm volatile("cp.async.cg.shared.global [%0], [%1], 16;"
                 :: "r"(dst), "l"(src));
}

#define CP_COMMIT()  asm volatile("cp.async.commit_group;" ::: "memory")
#define CP_WAIT0()   asm volatile("cp.async.wait_group 0;" ::: "memory")
#define CP_WAIT1()   asm volatile("cp.async.wait_group 1;" ::: "memory")
#define FENCE_ASYNC() asm volatile("fence.proxy.async.shared::cta;" ::: "memory")
#define MBAR_INIT(a, cnt) \
    asm volatile("mbarrier.init.shared.b64 [%0], %1;" :: "r"(a), "r"(cnt) : "memory")

#define SW128u(o) ((uint32_t)(o) ^ ((((uint32_t)(o)) >> 3) & 0x70u))
#define DESC_BASE ((2ull << 61) | (1ull << 46) | (64ull << 32) | (1ull << 16))
#define MAKE_DESC(a) (DESC_BASE | (((uint64_t)((a) >> 4)) & 0x3FFFull))
// idesc: fp32 accum, bf16 A/B, K-major, M=128, N=128
#define IDESC_128 (0x10u | 0x80u | 0x400u | (16u << 17) | (8u << 24))

#if USE_TCGEN05
__device__ __forceinline__ uint32_t elect1() {
    uint32_t p;
    asm volatile("{ .reg .pred p; elect.sync _|p, 0xFFFFFFFF; selp.b32 %0,1,0,p; }"
                 : "=r"(p));
    return p;
}

__device__ __forceinline__ void mbar_wait(uint32_t mbar, uint32_t parity) {
    asm volatile(
        "{\n\t.reg .pred P;\n\t"
        "WL_%=:\n\t"
        "mbarrier.try_wait.parity.acquire.cta.shared::cta.b64 P, [%0], %1, 0x989680;\n\t"
        "@P bra.uni WD_%=;\n\t"
        "bra.uni WL_%=;\n\t"
        "WD_%=:\n\t}"
        :: "r"(mbar), "r"(parity) : "memory");
}

#define TC_ALLOC(a, n) \
    asm volatile("tcgen05.alloc.cta_group::1.sync.aligned.shared::cta.b32 [%0], %1;" \
                 :: "r"(a), "r"(n) : "memory")
#define TC_DEALLOC(t, n) \
    asm volatile("tcgen05.dealloc.cta_group::1.sync.aligned.b32 %0, %1;" :: "r"(t), "r"(n))
#define TC_RELINQ() \
    asm volatile("tcgen05.relinquish_alloc_permit.cta_group::1.sync.aligned;")
#define TC_COMMIT(m) \
    asm volatile("tcgen05.commit.cta_group::1.mbarrier::arrive::one.shared::cluster.b64 [%0];" \
                 :: "r"(m) : "memory")
#define TC_FENCE_AFTER()  asm volatile("tcgen05.fence::after_thread_sync;" ::: "memory")
#define TC_FENCE_BEFORE() asm volatile("tcgen05.fence::before_thread_sync;" ::: "memory")
#define TC_WAIT_LD()      asm volatile("tcgen05.wait::ld.sync.aligned;" ::: "memory")

__device__ __forceinline__ void mma_bf16_ss(uint32_t d, uint64_t ad, uint64_t bd,
                                            uint32_t idesc, uint32_t en) {
    asm volatile(
        "{\n\t.reg .pred p;\n\t"
        "setp.ne.u32 p, %4, 0;\n\t"
        "tcgen05.mma.cta_group::1.kind::f16 [%0], %1, %2, %3, {%5,%5,%5,%5}, p;\n\t}"
        :: "r"(d), "l"(ad), "l"(bd), "r"(idesc), "r"(en), "r"(0u) : "memory");
}

__device__ __forceinline__ void ldtm32(uint32_t* r, uint32_t taddr) {
    asm volatile(
        "tcgen05.ld.sync.aligned.32x32b.x32.b32 "
        "{%0, %1, %2, %3, %4, %5, %6, %7, %8, %9, %10, %11, %12, %13, %14, %15, "
        "%16, %17, %18, %19, %20, %21, %22, %23, %24, %25, %26, %27, %28, %29, %30, %31}, [%32];"
        : "=r"(r[0]), "=r"(r[1]), "=r"(r[2]), "=r"(r[3]), "=r"(r[4]), "=r"(r[5]),
          "=r"(r[6]), "=r"(r[7]), "=r"(r[8]), "=r"(r[9]), "=r"(r[10]), "=r"(r[11]),
          "=r"(r[12]), "=r"(r[13]), "=r"(r[14]), "=r"(r[15]), "=r"(r[16]), "=r"(r[17]),
          "=r"(r[18]), "=r"(r[19]), "=r"(r[20]), "=r"(r[21]), "=r"(r[22]), "=r"(r[23]),
          "=r"(r[24]), "=r"(r[25]), "=r"(r[26]), "=r"(r[27]), "=r"(r[28]), "=r"(r[29]),
          "=r"(r[30]), "=r"(r[31])
        : "r"(taddr));
}
#endif  // USE_TCGEN05

// Baseline-ISA warp MMA — fallback body
__device__ __forceinline__ void hmma16816(float* d, const uint32_t* a, const uint32_t* b) {
    asm volatile(
        "mma.sync.aligned.m16n8k16.row.col.f32.bf16.bf16.f32 "
        "{%0,%1,%2,%3}, {%4,%5,%6,%7}, {%8,%9}, {%0,%1,%2,%3};"
        : "+f"(d[0]), "+f"(d[1]), "+f"(d[2]), "+f"(d[3])
        : "r"(a[0]), "r"(a[1]), "r"(a[2]), "r"(a[3]), "r"(b[0]), "r"(b[1]));
}

__device__ __forceinline__ void split_bf16(float v, __nv_bfloat16& hi, __nv_bfloat16& lo) {
    hi = __float2bfloat16(v);
    lo = __float2bfloat16(v - __bfloat162float(hi));
}

// ---------------------------------------------------------------------------
// Weight prep: concatenated transposed split weights.
// T[n][k]: n<1536 -> Wa[k][n] (Na=1536), else Wb[k][n-1536] (Nb=512); k>=Korig -> 0
// ---------------------------------------------------------------------------
__global__ void prep_wcat_kernel(const float* __restrict__ Wa,
                                 const float* __restrict__ Wb,
                                 __nv_bfloat16* __restrict__ Thi,
                                 __nv_bfloat16* __restrict__ Tlo,
                                 int Korig, int Kpad)
{
    int idx = blockIdx.x * blockDim.x + threadIdx.x;
    if (idx >= NCAT * Kpad) return;
    int n = idx / Kpad;
    int k = idx - n * Kpad;
    float v = 0.f;
    if (k < Korig)
        v = (n < 1536) ? Wa[(size_t)k * 1536 + n] : Wb[(size_t)k * 512 + (n - 1536)];
    __nv_bfloat16 hi, lo;
    split_bf16(v, hi, lo);
    Thi[idx] = hi;
    Tlo[idx] = lo;
}

// ---------------------------------------------------------------------------
// Embedding gather + split
// ---------------------------------------------------------------------------
__global__ void gather_x_kernel(const float* __restrict__ embed,
                                const int* __restrict__ vix,
                                const float* __restrict__ tmask,
                                __nv_bfloat16* __restrict__ xhi,
                                __nv_bfloat16* __restrict__ xlo)
{
    int idx = blockIdx.x * blockDim.x + threadIdx.x;
    const int QE = EPAD / 2;  // 160
    if (idx >= Nn * QE) return;
    int n = idx / QE;
    int e = (idx - n * QE) * 2;
    float m = tmask[n];
    float v0 = 0.f, v1 = 0.f;
    if (e < Ee) {
        const float* er = embed + (size_t)vix[n] * Ee + e;
        v0 = er[0] * m;
        v1 = er[1] * m;
    }
    __nv_bfloat16 h0, l0, h1, l1;
    split_bf16(v0, h0, l0);
    split_bf16(v1, h1, l1);
    *(__nv_bfloat162*)(xhi + (size_t)n * EPAD + e) = __nv_bfloat162(h0, h1);
    *(__nv_bfloat162*)(xlo + (size_t)n * EPAD + e) = __nv_bfloat162(l0, l1);
}

// ---------------------------------------------------------------------------
// Split-bf16 GEMM: C[M,Ncol] = (Ahi+Alo)[M,Ks] @ (Bhi+Blo)[Ncol,Ks]^T
// Grid.x may cover only a prefix of Ncol/128 column tiles (leaf level).
// ---------------------------------------------------------------------------
__global__ void __launch_bounds__(256)
gemm_split_kernel(const __nv_bfloat16* __restrict__ Ahi,
                  const __nv_bfloat16* __restrict__ Alo,
                  const __nv_bfloat16* __restrict__ Bhi,
                  const __nv_bfloat16* __restrict__ Blo,
                  float* __restrict__ C,
                  int M, int Ks, int Ncol)
{
#if USE_TCGEN05
    extern __shared__ char smem_raw[];
    const uint32_t sb = smem_u32(smem_raw);
    const uint32_t ctrl = sb;                               // tmem ptr @0, mbar @8,@16
    const uint32_t tiles = (sb + 64 + 1023) & ~1023u;

    const int tid = threadIdx.x;
    const int wid = tid >> 5;
    const int lid = tid & 31;
    const int m0 = blockIdx.y * 128;
    const int n0 = blockIdx.x * 128;
    const int NC = Ks >> 6;

    if (wid == 0) TC_ALLOC(ctrl, 128);
    if (tid == 0) { MBAR_INIT(ctrl + 8, 1); MBAR_INIT(ctrl + 16, 1); }
    __syncthreads();
    uint32_t tmem;
    asm("ld.shared.b32 %0, [%1];" : "=r"(tmem) : "r"(ctrl));

    auto load_chunk = [&](int buf, int k0) {
        uint32_t tb = tiles + buf * 65536;
#pragma unroll
        for (int q = tid; q < 1024; q += 256) {
            int row = q >> 3;
            int c = q & 7;
            uint32_t soff = SW128u(row * 128 + c * 16);
            size_t ao = (size_t)(m0 + row) * Ks + k0 + c * 8;
            size_t bo = (size_t)(n0 + row) * Ks + k0 + c * 8;
            cp16(tb + soff,         Ahi + ao);
            cp16(tb + 16384 + soff, Alo + ao);
            cp16(tb + 32768 + soff, Bhi + bo);
            cp16(tb + 49152 + soff, Blo + bo);
        }
        CP_COMMIT();
    };

    uint32_t ph0 = 0, ph1 = 0;
    load_chunk(0, 0);

    for (int c = 0; c < NC; c++) {
        const int cur = c & 1;
        const int nxt = cur ^ 1;

        CP_WAIT0();
        FENCE_ASYNC();
        __syncthreads();

        if (c >= 1) {
            uint32_t mb = ctrl + 8 + nxt * 8;
            uint32_t ph = nxt ? ph1 : ph0;
            mbar_wait(mb, ph);
            if (nxt) ph1 ^= 1; else ph0 ^= 1;
        }
        if (c + 1 < NC) load_chunk(nxt, (c + 1) * 64);

        if (wid == 0 && elect1()) {
            uint32_t tb = tiles + cur * 65536;
            uint64_t dah = MAKE_DESC(tb);
            uint64_t dal = MAKE_DESC(tb + 16384);
            uint64_t dbh = MAKE_DESC(tb + 32768);
            uint64_t dbl = MAKE_DESC(tb + 49152);
#pragma unroll
            for (int ks = 0; ks < 4; ks++)
                mma_bf16_ss(tmem, dah + 2 * ks, dbh + 2 * ks, IDESC_128,
                            (c == 0 && ks == 0) ? 0u : 1u);
#pragma unroll
            for (int ks = 0; ks < 4; ks++)
                mma_bf16_ss(tmem, dah + 2 * ks, dbl + 2 * ks, IDESC_128, 1u);
#pragma unroll
            for (int ks = 0; ks < 4; ks++)
                mma_bf16_ss(tmem, dal + 2 * ks, dbh + 2 * ks, IDESC_128, 1u);
            TC_COMMIT(ctrl + 8 + cur * 8);
        }
    }

    {
        const int last = (NC - 1) & 1;
        uint32_t ph = last ? ph1 : ph0;
        mbar_wait(ctrl + 8 + last * 8, ph);
    }
    TC_FENCE_AFTER();

    if (wid < 4) {
        float* crow = C + (size_t)(m0 + wid * 32 + lid) * Ncol + n0;
#pragma unroll
        for (int b = 0; b < 4; b++) {
            uint32_t r[32];
            ldtm32(r, tmem + b * 32);
            TC_WAIT_LD();
#pragma unroll
            for (int j = 0; j < 32; j += 4) {
                float4 v;
                v.x = __uint_as_float(r[j + 0]);
                v.y = __uint_as_float(r[j + 1]);
                v.z = __uint_as_float(r[j + 2]);
                v.w = __uint_as_float(r[j + 3]);
                *(float4*)(crow + b * 32 + j) = v;
            }
        }
        TC_FENCE_BEFORE();
    }

    __syncthreads();
    if (wid == 0) {
        TC_RELINQ();
        TC_DEALLOC(tmem, 128);
    }

#else  // ------------------------- mma.sync fallback -------------------------
    extern __shared__ char smem_raw[];
    const int tid = threadIdx.x;
    const int wid = tid >> 5;
    const int lane = tid & 31;
    const int wm = wid >> 1;
    const int wn = wid & 1;
    const int r4 = lane >> 2;
    const int tig = lane & 3;
    const int m0 = blockIdx.y * 128;
    const int n0 = blockIdx.x * 128;
    const int NC = Ks >> 5;

    float acc[2][8][4];
#pragma unroll
    for (int i = 0; i < 2; i++)
#pragma unroll
        for (int j = 0; j < 8; j++)
#pragma unroll
            for (int v = 0; v < 4; v++) acc[i][j][v] = 0.f;

    auto ldtile = [&](int buf, int k0) {
        uint32_t tb = smem_u32(smem_raw) + buf * 40960;
#pragma unroll
        for (int q = tid; q < 512; q += 256) {
            int row = q >> 2;
            int c = q & 3;
            uint32_t d = tb + row * 80 + c * 16;
            size_t ao = (size_t)(m0 + row) * Ks + k0 + c * 8;
            size_t bo = (size_t)(n0 + row) * Ks + k0 + c * 8;
            cp16(d,         Ahi + ao);
            cp16(d + 10240, Alo + ao);
            cp16(d + 20480, Bhi + bo);
            cp16(d + 30720, Blo + bo);
        }
        CP_COMMIT();
    };

    ldtile(0, 0);

    for (int c = 0; c < NC; c++) {
        const int cur = c & 1;
        if (c + 1 < NC) {
            ldtile(cur ^ 1, (c + 1) * 32);
            CP_WAIT1();
        } else {
            CP_WAIT0();
        }
        __syncthreads();

        const char* tb = smem_raw + cur * 40960;
#pragma unroll
        for (int kk = 0; kk < 32; kk += 16) {
            uint32_t ahi[2][4], alo[2][4], bhi[8][2], blo[8][2];
#pragma unroll
            for (int mi = 0; mi < 2; mi++) {
                int row = wm * 32 + mi * 16 + r4;
                int cb = (kk + tig * 2) * 2;
                ahi[mi][0] = *(const uint32_t*)(tb + row * 80 + cb);
                ahi[mi][1] = *(const uint32_t*)(tb + (row + 8) * 80 + cb);
                ahi[mi][2] = *(const uint32_t*)(tb + row * 80 + cb + 16);
                ahi[mi][3] = *(const uint32_t*)(tb + (row + 8) * 80 + cb + 16);
                alo[mi][0] = *(const uint32_t*)(tb + 10240 + row * 80 + cb);
                alo[mi][1] = *(const uint32_t*)(tb + 10240 + (row + 8) * 80 + cb);
                alo[mi][2] = *(const uint32_t*)(tb + 10240 + row * 80 + cb + 16);
                alo[mi][3] = *(const uint32_t*)(tb + 10240 + (row + 8) * 80 + cb + 16);
            }
#pragma unroll
            for (int ni = 0; ni < 8; ni++) {
                int nr = wn * 64 + ni * 8 + r4;
                int cb = (kk + tig * 2) * 2;
                bhi[ni][0] = *(const uint32_t*)(tb + 20480 + nr * 80 + cb);
                bhi[ni][1] = *(const uint32_t*)(tb + 20480 + nr * 80 + cb + 16);
                blo[ni][0] = *(const uint32_t*)(tb + 30720 + nr * 80 + cb);
                blo[ni][1] = *(const uint32_t*)(tb + 30720 + nr * 80 + cb + 16);
            }
#pragma unroll
            for (int mi = 0; mi < 2; mi++)
#pragma unroll
                for (int ni = 0; ni < 8; ni++) {
                    hmma16816(acc[mi][ni], ahi[mi], bhi[ni]);
                    hmma16816(acc[mi][ni], ahi[mi], blo[ni]);
                    hmma16816(acc[mi][ni], alo[mi], bhi[ni]);
                }
        }
        __syncthreads();
    }

#pragma unroll
    for (int mi = 0; mi < 2; mi++)
#pragma unroll
        for (int ni = 0; ni < 8; ni++) {
            int row = m0 + wm * 32 + mi * 16 + r4;
            int col = n0 + wn * 64 + ni * 8 + tig * 2;
            *(float2*)(C + (size_t)row * Ncol + col) =
                make_float2(acc[mi][ni][0], acc[mi][ni][1]);
            *(float2*)(C + (size_t)(row + 8) * Ncol + col) =
                make_float2(acc[mi][ni][2], acc[mi][ni][3]);
        }
#endif
}

// ---------------------------------------------------------------------------
// Node update (fused gates + output-side child gathers + h split)
//   iou_j  = xw4[n][j..] + sum_k m_k * hu4[ci_k][j..] + b_iou
//   f_kj   = sigmoid(xw4[n][1536+j] + b_f[j] + m_k * hu4[ci_k][1536+j])
//   fc     = sum_k f_kj * c_prev[ci_k][j] * m_k
//   c = sig(i)*tanh(u) + fc ; h = sig(o)*tanh(c) -> split to hhi/hlo (+opt f32)
// ---------------------------------------------------------------------------
__device__ __forceinline__ float sigmoidf_(float v) {
    return 1.f / (1.f + __expf(-v));
}

template <bool LEAF>
__global__ void node_update_kernel(const float* __restrict__ xw4,
                                   const float* __restrict__ hu4,
                                   const float* __restrict__ b_iou,
                                   const float* __restrict__ b_f,
                                   const int* __restrict__ cidx,
                                   const float* __restrict__ cmask,
                                   const float* __restrict__ c_prev,
                                   float* __restrict__ c_out,
                                   __nv_bfloat16* __restrict__ hhi,
                                   __nv_bfloat16* __restrict__ hlo,
                                   float* __restrict__ h_f32)   // may be null
{
    int idx = blockIdx.x * blockDim.x + threadIdx.x;   // over Nn * Hh/2
    if (idx >= Nn * (Hh / 2)) return;
    int n = idx >> 8;              // / 256
    int j = (idx & 255) * 2;

    const float* xw = xw4 + (size_t)n * NCAT;
    float2 gi = *(const float2*)(xw + j);
    float2 go = *(const float2*)(xw + 512 + j);
    float2 gu = *(const float2*)(xw + 1024 + j);
    {
        float2 b0 = *(const float2*)(b_iou + j);
        float2 b1 = *(const float2*)(b_iou + 512 + j);
        float2 b2 = *(const float2*)(b_iou + 1024 + j);
        gi.x += b0.x; gi.y += b0.y;
        go.x += b1.x; go.y += b1.y;
        gu.x += b2.x; gu.y += b2.y;
    }

    float fcx = 0.f, fcy = 0.f;
    if (!LEAF) {
        float2 bf = *(const float2*)(b_f + j);
        float2 xf = *(const float2*)(xw + 1536 + j);
        xf.x += bf.x; xf.y += bf.y;
#pragma unroll
        for (int k = 0; k < Kk; k++) {
            int ci = cidx[n * Kk + k];
            float m = cmask[n * Kk + k];
            const float* hr = hu4 + (size_t)ci * NCAT;
            float2 hi_ = *(const float2*)(hr + j);
            float2 ho_ = *(const float2*)(hr + 512 + j);
            float2 hu_ = *(const float2*)(hr + 1024 + j);
            float2 hf_ = *(const float2*)(hr + 1536 + j);
            gi.x += m * hi_.x; gi.y += m * hi_.y;
            go.x += m * ho_.x; go.y += m * ho_.y;
            gu.x += m * hu_.x; gu.y += m * hu_.y;
            float fx = sigmoidf_(xf.x + m * hf_.x);
            float fy = sigmoidf_(xf.y + m * hf_.y);
            float2 cpv = *(const float2*)(c_prev + (size_t)ci * Hh + j);
            fcx += fx * cpv.x * m;
            fcy += fy * cpv.y * m;
        }
    }

    float cx = sigmoidf_(gi.x) * tanhf(gu.x) + fcx;
    float cy = sigmoidf_(gi.y) * tanhf(gu.y) + fcy;
    *(float2*)(c_out + (size_t)n * Hh + j) = make_float2(cx, cy);

    float hx = sigmoidf_(go.x) * tanhf(cx);
    float hy = sigmoidf_(go.y) * tanhf(cy);

    __nv_bfloat16 h0, l0, h1, l1;
    split_bf16(hx, h0, l0);
    split_bf16(hy, h1, l1);
    *(__nv_bfloat162*)(hhi + (size_t)n * Hh + j) = __nv_bfloat162(h0, h1);
    *(__nv_bfloat162*)(hlo + (size_t)n * Hh + j) = __nv_bfloat162(l0, l1);
    if (h_f32)
        *(float2*)(h_f32 + (size_t)n * Hh + j) = make_float2(hx, hy);
}

// ---------------------------------------------------------------------------
// Launch
// ---------------------------------------------------------------------------
extern "C" void kernel_launch(void* const* d_in, const int* in_sizes, int n_in,
                              void* d_out, int out_size)
{
    const int*   vocab_ix   = (const int*)d_in[0];
    const int*   child_idx  = (const int*)d_in[1];
    const float* token_mask = (const float*)d_in[2];
    const float* child_mask = (const float*)d_in[3];
    const float* embed      = (const float*)d_in[4];
    const float* W_iou      = (const float*)d_in[5];   // [E, 3H]
    const float* U_iou      = (const float*)d_in[6];   // [H, 3H]
    const float* b_iou      = (const float*)d_in[7];
    const float* W_f        = (const float*)d_in[8];   // [E, H]
    const float* U_f        = (const float*)d_in[9];   // [H, H]
    const float* b_f        = (const float*)d_in[10];
    float* out = (float*)d_out;

    static const int GEMM_SMEM = 133120;
    cudaFuncSetAttribute(gemm_split_kernel,
                         cudaFuncAttributeMaxDynamicSharedMemorySize, GEMM_SMEM);

    __nv_bfloat16 *xhi, *xlo, *hhi, *hlo;
    __nv_bfloat16 *WcatThi, *WcatTlo, *UcatThi, *UcatTlo;
    float *xw4, *hu4, *cbuf;
    cudaGetSymbolAddress((void**)&xhi, g_xhi);
    cudaGetSymbolAddress((void**)&xlo, g_xlo);
    cudaGetSymbolAddress((void**)&hhi, g_hhi);
    cudaGetSymbolAddress((void**)&hlo, g_hlo);
    cudaGetSymbolAddress((void**)&WcatThi, g_WcatT_hi);
    cudaGetSymbolAddress((void**)&WcatTlo, g_WcatT_lo);
    cudaGetSymbolAddress((void**)&UcatThi, g_UcatT_hi);
    cudaGetSymbolAddress((void**)&UcatTlo, g_UcatT_lo);
    cudaGetSymbolAddress((void**)&xw4, g_xw4);
    cudaGetSymbolAddress((void**)&hu4, g_hu4);
    cudaGetSymbolAddress((void**)&cbuf, g_cbuf);

    float* cp[2] = { cbuf, cbuf + (size_t)Nn * Hh };

    const int T = 256;

    // Weight prep (constant across levels)
    prep_wcat_kernel<<<(NCAT * EPAD + T - 1) / T, T>>>(W_iou, W_f, WcatThi, WcatTlo, Ee, EPAD);
    prep_wcat_kernel<<<(NCAT * Hh + T - 1) / T, T>>>(U_iou, U_f, UcatThi, UcatTlo, Hh, Hh);

    const int gx_blocks = (Nn * (EPAD / 2) + T - 1) / T;
    const int nu_blocks = (Nn * (Hh / 2) + T - 1) / T;

    int cur = 0;
    for (int l = Ll - 1; l >= 0; --l) {
        const bool leaf = (l == Ll - 1);
        const int prev = cur ^ 1;

        gather_x_kernel<<<gx_blocks, T>>>(embed, vocab_ix + l * Nn,
                                          token_mask + l * Nn, xhi, xlo);

        // xw4 = x @ [W_iou | W_f]  (leaf: only the iou column tiles)
        gemm_split_kernel<<<dim3(leaf ? 12 : 16, Nn / 128), 256, GEMM_SMEM>>>(
            xhi, xlo, WcatThi, WcatTlo, xw4, Nn, EPAD, NCAT);

        if (!leaf) {
            // hu4 = h_prev @ [U_iou | U_f]
            gemm_split_kernel<<<dim3(16, Nn / 128), 256, GEMM_SMEM>>>(
                hhi, hlo, UcatThi, UcatTlo, hu4, Nn, Hh, NCAT);
        }

        float* hf32 = (l == 0) ? out : nullptr;
        if (leaf) {
            node_update_kernel<true><<<nu_blocks, T>>>(
                xw4, nullptr, b_iou, b_f,
                nullptr, nullptr, nullptr, cp[cur], hhi, hlo, hf32);
        } else {
            node_update_kernel<false><<<nu_blocks, T>>>(
                xw4, hu4, b_iou, b_f,
                child_idx + l * Nn * Kk, child_mask + l * Nn * Kk,
                cp[prev], cp[cur], hhi, hlo, hf32);
        }
        cur ^= 1;
    }
}

// round 5
// speedup vs baseline: 6.2654x; 1.0586x over previous
#include <cuda_runtime.h>
#include <cuda_bf16.h>
#include <math.h>
#include <stdint.h>

// Problem constants
#define Vv 50000
#define Ee 300
#define EPAD 320
#define Hh 512
#define Ll 6
#define Nn 8192
#define Kk 4
#define NCAT 2048   // [iou (1536) | f (512)] concatenated output columns

// ---------------------------------------------------------------------------
// Feature gate: tcgen05 exists only on arch-accelerated / family passes.
// ---------------------------------------------------------------------------
#if defined(__CUDA_ARCH__) && (defined(__CUDA_ARCH_FEAT_SM103_ALL) || \
    defined(__CUDA_ARCH_FEAT_SM100_ALL) || defined(__CUDA_ARCH_FEAT_SM110_ALL) || \
    (defined(__CUDA_ARCH_FAMILY_SPECIFIC__) && (__CUDA_ARCH_FAMILY_SPECIFIC__ >= 1000)))
#define USE_TCGEN05 1
#else
#define USE_TCGEN05 0
#endif

// ---------------------------------------------------------------------------
// Scratch
// ---------------------------------------------------------------------------
__device__ __nv_bfloat16 g_xhi[Ll * Nn * EPAD];   // all levels batched
__device__ __nv_bfloat16 g_xlo[Ll * Nn * EPAD];
__device__ __nv_bfloat16 g_hhi[Nn * Hh];
__device__ __nv_bfloat16 g_hlo[Nn * Hh];

__device__ __nv_bfloat16 g_WcatT_hi[NCAT * EPAD];
__device__ __nv_bfloat16 g_WcatT_lo[NCAT * EPAD];
__device__ __nv_bfloat16 g_UcatT_hi[NCAT * Hh];
__device__ __nv_bfloat16 g_UcatT_lo[NCAT * Hh];

__device__ float g_xw4[Nn * NCAT];   // x @ [W_iou|W_f] (per level)
__device__ float g_hu4[Nn * NCAT];   // h @ [U_iou|U_f]
__device__ float g_cbuf[2 * Nn * Hh];

// ---------------------------------------------------------------------------
// Common PTX helpers
// ---------------------------------------------------------------------------
__device__ __forceinline__ uint32_t smem_u32(const void* p) {
    uint32_t a;
    asm("{ .reg .u64 t; cvta.to.shared.u64 t, %1; cvt.u32.u64 %0, t; }"
        : "=r"(a) : "l"(p));
    return a;
}

__device__ __forceinline__ void cp16(uint32_t dst, const void* src) {
    asm volatile("cp.async.cg.shared.global [%0], [%1], 16;"
                 :: "r"(dst), "l"(src));
}

#define CP_COMMIT()  asm volatile("cp.async.commit_group;" ::: "memory")
#define CP_WAIT0()   asm volatile("cp.async.wait_group 0;" ::: "memory")
#define CP_WAIT1()   asm volatile("cp.async.wait_group 1;" ::: "memory")
#define FENCE_ASYNC() asm volatile("fence.proxy.async.shared::cta;" ::: "memory")
#define MBAR_INIT(a, cnt) \
    asm volatile("mbarrier.init.shared.b64 [%0], %1;" :: "r"(a), "r"(cnt) : "memory")

#define SW128u(o) ((uint32_t)(o) ^ ((((uint32_t)(o)) >> 3) & 0x70u))
#define DESC_BASE ((2ull << 61) | (1ull << 46) | (64ull << 32) | (1ull << 16))
#define MAKE_DESC(a) (DESC_BASE | (((uint64_t)((a) >> 4)) & 0x3FFFull))
// idesc: fp32 accum, bf16 A/B, K-major, M=128, N=256
#define IDESC_N256 (0x10u | 0x80u | 0x400u | (32u << 17) | (8u << 24))

#if USE_TCGEN05
__device__ __forceinline__ uint32_t elect1() {
    uint32_t p;
    asm volatile("{ .reg .pred p; elect.sync _|p, 0xFFFFFFFF; selp.b32 %0,1,0,p; }"
                 : "=r"(p));
    return p;
}

__device__ __forceinline__ void mbar_wait(uint32_t mbar, uint32_t parity) {
    asm volatile(
        "{\n\t.reg .pred P;\n\t"
        "WL_%=:\n\t"
        "mbarrier.try_wait.parity.acquire.cta.shared::cta.b64 P, [%0], %1, 0x989680;\n\t"
        "@P bra.uni WD_%=;\n\t"
        "bra.uni WL_%=;\n\t"
        "WD_%=:\n\t}"
        :: "r"(mbar), "r"(parity) : "memory");
}

#define TC_ALLOC(a, n) \
    asm volatile("tcgen05.alloc.cta_group::1.sync.aligned.shared::cta.b32 [%0], %1;" \
                 :: "r"(a), "r"(n) : "memory")
#define TC_DEALLOC(t, n) \
    asm volatile("tcgen05.dealloc.cta_group::1.sync.aligned.b32 %0, %1;" :: "r"(t), "r"(n))
#define TC_RELINQ() \
    asm volatile("tcgen05.relinquish_alloc_permit.cta_group::1.sync.aligned;")
#define TC_COMMIT(m) \
    asm volatile("tcgen05.commit.cta_group::1.mbarrier::arrive::one.shared::cluster.b64 [%0];" \
                 :: "r"(m) : "memory")
#define TC_FENCE_AFTER()  asm volatile("tcgen05.fence::after_thread_sync;" ::: "memory")
#define TC_FENCE_BEFORE() asm volatile("tcgen05.fence::before_thread_sync;" ::: "memory")
#define TC_WAIT_LD()      asm volatile("tcgen05.wait::ld.sync.aligned;" ::: "memory")

__device__ __forceinline__ void mma_bf16_ss(uint32_t d, uint64_t ad, uint64_t bd,
                                            uint32_t idesc, uint32_t en) {
    asm volatile(
        "{\n\t.reg .pred p;\n\t"
        "setp.ne.u32 p, %4, 0;\n\t"
        "tcgen05.mma.cta_group::1.kind::f16 [%0], %1, %2, %3, {%5,%5,%5,%5}, p;\n\t}"
        :: "r"(d), "l"(ad), "l"(bd), "r"(idesc), "r"(en), "r"(0u) : "memory");
}

__device__ __forceinline__ void ldtm32(uint32_t* r, uint32_t taddr) {
    asm volatile(
        "tcgen05.ld.sync.aligned.32x32b.x32.b32 "
        "{%0, %1, %2, %3, %4, %5, %6, %7, %8, %9, %10, %11, %12, %13, %14, %15, "
        "%16, %17, %18, %19, %20, %21, %22, %23, %24, %25, %26, %27, %28, %29, %30, %31}, [%32];"
        : "=r"(r[0]), "=r"(r[1]), "=r"(r[2]), "=r"(r[3]), "=r"(r[4]), "=r"(r[5]),
          "=r"(r[6]), "=r"(r[7]), "=r"(r[8]), "=r"(r[9]), "=r"(r[10]), "=r"(r[11]),
          "=r"(r[12]), "=r"(r[13]), "=r"(r[14]), "=r"(r[15]), "=r"(r[16]), "=r"(r[17]),
          "=r"(r[18]), "=r"(r[19]), "=r"(r[20]), "=r"(r[21]), "=r"(r[22]), "=r"(r[23]),
          "=r"(r[24]), "=r"(r[25]), "=r"(r[26]), "=r"(r[27]), "=r"(r[28]), "=r"(r[29]),
          "=r"(r[30]), "=r"(r[31])
        : "r"(taddr));
}
#endif  // USE_TCGEN05

// Baseline-ISA warp MMA — fallback body
__device__ __forceinline__ void hmma16816(float* d, const uint32_t* a, const uint32_t* b) {
    asm volatile(
        "mma.sync.aligned.m16n8k16.row.col.f32.bf16.bf16.f32 "
        "{%0,%1,%2,%3}, {%4,%5,%6,%7}, {%8,%9}, {%0,%1,%2,%3};"
        : "+f"(d[0]), "+f"(d[1]), "+f"(d[2]), "+f"(d[3])
        : "r"(a[0]), "r"(a[1]), "r"(a[2]), "r"(a[3]), "r"(b[0]), "r"(b[1]));
}

__device__ __forceinline__ void split_bf16(float v, __nv_bfloat16& hi, __nv_bfloat16& lo) {
    hi = __float2bfloat16(v);
    lo = __float2bfloat16(v - __bfloat162float(hi));
}

// ---------------------------------------------------------------------------
// Weight prep: concatenated transposed split weights.
// ---------------------------------------------------------------------------
__global__ void prep_wcat_kernel(const float* __restrict__ Wa,
                                 const float* __restrict__ Wb,
                                 __nv_bfloat16* __restrict__ Thi,
                                 __nv_bfloat16* __restrict__ Tlo,
                                 int Korig, int Kpad)
{
    int idx = blockIdx.x * blockDim.x + threadIdx.x;
    if (idx >= NCAT * Kpad) return;
    int n = idx / Kpad;
    int k = idx - n * Kpad;
    float v = 0.f;
    if (k < Korig)
        v = (n < 1536) ? Wa[(size_t)k * 1536 + n] : Wb[(size_t)k * 512 + (n - 1536)];
    __nv_bfloat16 hi, lo;
    split_bf16(v, hi, lo);
    Thi[idx] = hi;
    Tlo[idx] = lo;
}

// ---------------------------------------------------------------------------
// Embedding gather + split, ALL levels in one launch
// ---------------------------------------------------------------------------
__global__ void gather_x_all_kernel(const float* __restrict__ embed,
                                    const int* __restrict__ vix,     // [L*N]
                                    const float* __restrict__ tmask, // [L*N]
                                    __nv_bfloat16* __restrict__ xhi,
                                    __nv_bfloat16* __restrict__ xlo)
{
    int idx = blockIdx.x * blockDim.x + threadIdx.x;
    const int QE = EPAD / 2;  // 160
    if (idx >= Ll * Nn * QE) return;
    int n = idx / QE;                 // 0 .. L*N-1
    int e = (idx - n * QE) * 2;
    float m = tmask[n];
    float v0 = 0.f, v1 = 0.f;
    if (e < Ee) {
        const float* er = embed + (size_t)vix[n] * Ee + e;
        v0 = er[0] * m;
        v1 = er[1] * m;
    }
    __nv_bfloat16 h0, l0, h1, l1;
    split_bf16(v0, h0, l0);
    split_bf16(v1, h1, l1);
    *(__nv_bfloat162*)(xhi + (size_t)n * EPAD + e) = __nv_bfloat162(h0, h1);
    *(__nv_bfloat162*)(xlo + (size_t)n * EPAD + e) = __nv_bfloat162(l0, l1);
}

// ---------------------------------------------------------------------------
// Split-bf16 GEMM: C[M,Ncol] = (Ahi+Alo)[M,Ks] @ (Bhi+Blo)[Ncol,Ks]^T
// Tile: 128 (M) x 256 (N) per CTA, K-chunks of 64, 2-stage cp.async pipeline.
// ---------------------------------------------------------------------------
#define STAGE_BYTES 98304   // Ahi 16K | Alo 16K | Bhi 32K | Blo 32K
#define GEMM_SMEM   (2 * STAGE_BYTES + 1024)

__global__ void __launch_bounds__(256)
gemm_split_kernel(const __nv_bfloat16* __restrict__ Ahi,
                  const __nv_bfloat16* __restrict__ Alo,
                  const __nv_bfloat16* __restrict__ Bhi,
                  const __nv_bfloat16* __restrict__ Blo,
                  float* __restrict__ C,
                  int M, int Ks, int Ncol)
{
#if USE_TCGEN05
    extern __shared__ char smem_raw[];
    const uint32_t sb = smem_u32(smem_raw);
    const uint32_t ctrl = sb;                               // tmem ptr @0, mbar @8,@16
    const uint32_t tiles = (sb + 64 + 1023) & ~1023u;

    const int tid = threadIdx.x;
    const int wid = tid >> 5;
    const int lid = tid & 31;
    const int m0 = blockIdx.y * 128;
    const int n0 = blockIdx.x * 256;
    const int NC = Ks >> 6;

    if (wid == 0) TC_ALLOC(ctrl, 256);
    if (tid == 0) { MBAR_INIT(ctrl + 8, 1); MBAR_INIT(ctrl + 16, 1); }
    __syncthreads();
    uint32_t tmem;
    asm("ld.shared.b32 %0, [%1];" : "=r"(tmem) : "r"(ctrl));

    // Stage layout: base + {Ahi:0, Alo:16K, Bhi:32K, Blo:64K}
    auto load_chunk = [&](int buf, int k0) {
        uint32_t tb = tiles + buf * STAGE_BYTES;
#pragma unroll
        for (int q = tid; q < 1024; q += 256) {           // A: 128 rows x 8
            int row = q >> 3;
            int c = q & 7;
            uint32_t soff = SW128u(row * 128 + c * 16);
            size_t ao = (size_t)(m0 + row) * Ks + k0 + c * 8;
            cp16(tb + soff,         Ahi + ao);
            cp16(tb + 16384 + soff, Alo + ao);
        }
#pragma unroll
        for (int q = tid; q < 2048; q += 256) {           // B: 256 rows x 8
            int row = q >> 3;
            int c = q & 7;
            uint32_t soff = SW128u(row * 128 + c * 16);
            size_t bo = (size_t)(n0 + row) * Ks + k0 + c * 8;
            cp16(tb + 32768 + soff, Bhi + bo);
            cp16(tb + 65536 + soff, Blo + bo);
        }
        CP_COMMIT();
    };

    uint32_t ph0 = 0, ph1 = 0;
    load_chunk(0, 0);

    for (int c = 0; c < NC; c++) {
        const int cur = c & 1;
        const int nxt = cur ^ 1;

        CP_WAIT0();
        FENCE_ASYNC();
        __syncthreads();

        if (c >= 1) {
            uint32_t mb = ctrl + 8 + nxt * 8;
            uint32_t ph = nxt ? ph1 : ph0;
            mbar_wait(mb, ph);
            if (nxt) ph1 ^= 1; else ph0 ^= 1;
        }
        if (c + 1 < NC) load_chunk(nxt, (c + 1) * 64);

        if (wid == 0 && elect1()) {
            uint32_t tb = tiles + cur * STAGE_BYTES;
            uint64_t dah = MAKE_DESC(tb);
            uint64_t dal = MAKE_DESC(tb + 16384);
            uint64_t dbh = MAKE_DESC(tb + 32768);
            uint64_t dbl = MAKE_DESC(tb + 65536);
#pragma unroll
            for (int ks = 0; ks < 4; ks++)
                mma_bf16_ss(tmem, dah + 2 * ks, dbh + 2 * ks, IDESC_N256,
                            (c == 0 && ks == 0) ? 0u : 1u);
#pragma unroll
            for (int ks = 0; ks < 4; ks++)
                mma_bf16_ss(tmem, dah + 2 * ks, dbl + 2 * ks, IDESC_N256, 1u);
#pragma unroll
            for (int ks = 0; ks < 4; ks++)
                mma_bf16_ss(tmem, dal + 2 * ks, dbh + 2 * ks, IDESC_N256, 1u);
            TC_COMMIT(ctrl + 8 + cur * 8);
        }
    }

    {
        const int last = (NC - 1) & 1;
        uint32_t ph = last ? ph1 : ph0;
        mbar_wait(ctrl + 8 + last * 8, ph);
    }
    TC_FENCE_AFTER();

    if (wid < 4) {
        float* crow = C + (size_t)(m0 + wid * 32 + lid) * Ncol + n0;
#pragma unroll
        for (int b = 0; b < 8; b++) {
            uint32_t r[32];
            ldtm32(r, tmem + b * 32);
            TC_WAIT_LD();
#pragma unroll
            for (int j = 0; j < 32; j += 4) {
                float4 v;
                v.x = __uint_as_float(r[j + 0]);
                v.y = __uint_as_float(r[j + 1]);
                v.z = __uint_as_float(r[j + 2]);
                v.w = __uint_as_float(r[j + 3]);
                *(float4*)(crow + b * 32 + j) = v;
            }
        }
        TC_FENCE_BEFORE();
    }

    __syncthreads();
    if (wid == 0) {
        TC_RELINQ();
        TC_DEALLOC(tmem, 256);
    }

#else  // ------------------------- mma.sync fallback -------------------------
    extern __shared__ char smem_raw[];
    const int tid = threadIdx.x;
    const int wid = tid >> 5;
    const int lane = tid & 31;
    const int wm = wid >> 1;
    const int wn = wid & 1;
    const int r4 = lane >> 2;
    const int tig = lane & 3;
    const int m0 = blockIdx.y * 128;
    const int NC = Ks >> 5;

    for (int half = 0; half < 2; half++) {
        const int n0 = blockIdx.x * 256 + half * 128;

        float acc[2][8][4];
#pragma unroll
        for (int i = 0; i < 2; i++)
#pragma unroll
            for (int j = 0; j < 8; j++)
#pragma unroll
                for (int v = 0; v < 4; v++) acc[i][j][v] = 0.f;

        auto ldtile = [&](int buf, int k0) {
            uint32_t tb = smem_u32(smem_raw) + buf * 40960;
#pragma unroll
            for (int q = tid; q < 512; q += 256) {
                int row = q >> 2;
                int c = q & 3;
                uint32_t d = tb + row * 80 + c * 16;
                size_t ao = (size_t)(m0 + row) * Ks + k0 + c * 8;
                size_t bo = (size_t)(n0 + row) * Ks + k0 + c * 8;
                cp16(d,         Ahi + ao);
                cp16(d + 10240, Alo + ao);
                cp16(d + 20480, Bhi + bo);
                cp16(d + 30720, Blo + bo);
            }
            CP_COMMIT();
        };

        ldtile(0, 0);

        for (int c = 0; c < NC; c++) {
            const int cur = c & 1;
            if (c + 1 < NC) {
                ldtile(cur ^ 1, (c + 1) * 32);
                CP_WAIT1();
            } else {
                CP_WAIT0();
            }
            __syncthreads();

            const char* tb = smem_raw + cur * 40960;
#pragma unroll
            for (int kk = 0; kk < 32; kk += 16) {
                uint32_t ahi[2][4], alo[2][4], bhi[8][2], blo[8][2];
#pragma unroll
                for (int mi = 0; mi < 2; mi++) {
                    int row = wm * 32 + mi * 16 + r4;
                    int cb = (kk + tig * 2) * 2;
                    ahi[mi][0] = *(const uint32_t*)(tb + row * 80 + cb);
                    ahi[mi][1] = *(const uint32_t*)(tb + (row + 8) * 80 + cb);
                    ahi[mi][2] = *(const uint32_t*)(tb + row * 80 + cb + 16);
                    ahi[mi][3] = *(const uint32_t*)(tb + (row + 8) * 80 + cb + 16);
                    alo[mi][0] = *(const uint32_t*)(tb + 10240 + row * 80 + cb);
                    alo[mi][1] = *(const uint32_t*)(tb + 10240 + (row + 8) * 80 + cb);
                    alo[mi][2] = *(const uint32_t*)(tb + 10240 + row * 80 + cb + 16);
                    alo[mi][3] = *(const uint32_t*)(tb + 10240 + (row + 8) * 80 + cb + 16);
                }
#pragma unroll
                for (int ni = 0; ni < 8; ni++) {
                    int nr = wn * 64 + ni * 8 + r4;
                    int cb = (kk + tig * 2) * 2;
                    bhi[ni][0] = *(const uint32_t*)(tb + 20480 + nr * 80 + cb);
                    bhi[ni][1] = *(const uint32_t*)(tb + 20480 + nr * 80 + cb + 16);
                    blo[ni][0] = *(const uint32_t*)(tb + 30720 + nr * 80 + cb);
                    blo[ni][1] = *(const uint32_t*)(tb + 30720 + nr * 80 + cb + 16);
                }
#pragma unroll
                for (int mi = 0; mi < 2; mi++)
#pragma unroll
                    for (int ni = 0; ni < 8; ni++) {
                        hmma16816(acc[mi][ni], ahi[mi], bhi[ni]);
                        hmma16816(acc[mi][ni], ahi[mi], blo[ni]);
                        hmma16816(acc[mi][ni], alo[mi], bhi[ni]);
                    }
            }
            __syncthreads();
        }

#pragma unroll
        for (int mi = 0; mi < 2; mi++)
#pragma unroll
            for (int ni = 0; ni < 8; ni++) {
                int row = m0 + wm * 32 + mi * 16 + r4;
                int col = n0 + wn * 64 + ni * 8 + tig * 2;
                *(float2*)(C + (size_t)row * Ncol + col) =
                    make_float2(acc[mi][ni][0], acc[mi][ni][1]);
                *(float2*)(C + (size_t)(row + 8) * Ncol + col) =
                    make_float2(acc[mi][ni][2], acc[mi][ni][3]);
            }
        __syncthreads();
    }
#endif
}

// ---------------------------------------------------------------------------
// Node update (fused gates + output-side child gathers + h split)
// ---------------------------------------------------------------------------
__device__ __forceinline__ float sigmoidf_(float v) {
    return 1.f / (1.f + __expf(-v));
}

template <bool LEAF>
__global__ void node_update_kernel(const float* __restrict__ xw4,
                                   const float* __restrict__ hu4,
                                   const float* __restrict__ b_iou,
                                   const float* __restrict__ b_f,
                                   const int* __restrict__ cidx,
                                   const float* __restrict__ cmask,
                                   const float* __restrict__ c_prev,
                                   float* __restrict__ c_out,
                                   __nv_bfloat16* __restrict__ hhi,
                                   __nv_bfloat16* __restrict__ hlo,
                                   float* __restrict__ h_f32)   // may be null
{
    int idx = blockIdx.x * blockDim.x + threadIdx.x;   // over Nn * Hh/2
    if (idx >= Nn * (Hh / 2)) return;
    int n = idx >> 8;              // / 256
    int j = (idx & 255) * 2;

    const float* xw = xw4 + (size_t)n * NCAT;
    float2 gi = *(const float2*)(xw + j);
    float2 go = *(const float2*)(xw + 512 + j);
    float2 gu = *(const float2*)(xw + 1024 + j);
    {
        float2 b0 = *(const float2*)(b_iou + j);
        float2 b1 = *(const float2*)(b_iou + 512 + j);
        float2 b2 = *(const float2*)(b_iou + 1024 + j);
        gi.x += b0.x; gi.y += b0.y;
        go.x += b1.x; go.y += b1.y;
        gu.x += b2.x; gu.y += b2.y;
    }

    float fcx = 0.f, fcy = 0.f;
    if (!LEAF) {
        float2 bf = *(const float2*)(b_f + j);
        float2 xf = *(const float2*)(xw + 1536 + j);
        xf.x += bf.x; xf.y += bf.y;
#pragma unroll
        for (int k = 0; k < Kk; k++) {
            int ci = cidx[n * Kk + k];
            float m = cmask[n * Kk + k];
            const float* hr = hu4 + (size_t)ci * NCAT;
            float2 hi_ = *(const float2*)(hr + j);
            float2 ho_ = *(const float2*)(hr + 512 + j);
            float2 hu_ = *(const float2*)(hr + 1024 + j);
            float2 hf_ = *(const float2*)(hr + 1536 + j);
            gi.x += m * hi_.x; gi.y += m * hi_.y;
            go.x += m * ho_.x; go.y += m * ho_.y;
            gu.x += m * hu_.x; gu.y += m * hu_.y;
            float fx = sigmoidf_(xf.x + m * hf_.x);
            float fy = sigmoidf_(xf.y + m * hf_.y);
            float2 cpv = *(const float2*)(c_prev + (size_t)ci * Hh + j);
            fcx += fx * cpv.x * m;
            fcy += fy * cpv.y * m;
        }
    }

    float cx = sigmoidf_(gi.x) * tanhf(gu.x) + fcx;
    float cy = sigmoidf_(gi.y) * tanhf(gu.y) + fcy;
    *(float2*)(c_out + (size_t)n * Hh + j) = make_float2(cx, cy);

    float hx = sigmoidf_(go.x) * tanhf(cx);
    float hy = sigmoidf_(go.y) * tanhf(cy);

    __nv_bfloat16 h0, l0, h1, l1;
    split_bf16(hx, h0, l0);
    split_bf16(hy, h1, l1);
    *(__nv_bfloat162*)(hhi + (size_t)n * Hh + j) = __nv_bfloat162(h0, h1);
    *(__nv_bfloat162*)(hlo + (size_t)n * Hh + j) = __nv_bfloat162(l0, l1);
    if (h_f32)
        *(float2*)(h_f32 + (size_t)n * Hh + j) = make_float2(hx, hy);
}

// ---------------------------------------------------------------------------
// Launch
// ---------------------------------------------------------------------------
extern "C" void kernel_launch(void* const* d_in, const int* in_sizes, int n_in,
                              void* d_out, int out_size)
{
    const int*   vocab_ix   = (const int*)d_in[0];
    const int*   child_idx  = (const int*)d_in[1];
    const float* token_mask = (const float*)d_in[2];
    const float* child_mask = (const float*)d_in[3];
    const float* embed      = (const float*)d_in[4];
    const float* W_iou      = (const float*)d_in[5];   // [E, 3H]
    const float* U_iou      = (const float*)d_in[6];   // [H, 3H]
    const float* b_iou      = (const float*)d_in[7];
    const float* W_f        = (const float*)d_in[8];   // [E, H]
    const float* U_f        = (const float*)d_in[9];   // [H, H]
    const float* b_f        = (const float*)d_in[10];
    float* out = (float*)d_out;

    cudaFuncSetAttribute(gemm_split_kernel,
                         cudaFuncAttributeMaxDynamicSharedMemorySize, GEMM_SMEM);

    __nv_bfloat16 *xhi, *xlo, *hhi, *hlo;
    __nv_bfloat16 *WcatThi, *WcatTlo, *UcatThi, *UcatTlo;
    float *xw4, *hu4, *cbuf;
    cudaGetSymbolAddress((void**)&xhi, g_xhi);
    cudaGetSymbolAddress((void**)&xlo, g_xlo);
    cudaGetSymbolAddress((void**)&hhi, g_hhi);
    cudaGetSymbolAddress((void**)&hlo, g_hlo);
    cudaGetSymbolAddress((void**)&WcatThi, g_WcatT_hi);
    cudaGetSymbolAddress((void**)&WcatTlo, g_WcatT_lo);
    cudaGetSymbolAddress((void**)&UcatThi, g_UcatT_hi);
    cudaGetSymbolAddress((void**)&UcatTlo, g_UcatT_lo);
    cudaGetSymbolAddress((void**)&xw4, g_xw4);
    cudaGetSymbolAddress((void**)&hu4, g_hu4);
    cudaGetSymbolAddress((void**)&cbuf, g_cbuf);

    float* cp[2] = { cbuf, cbuf + (size_t)Nn * Hh };

    const int T = 256;

    // Weight prep + all-level x gather (independent of recurrence)
    prep_wcat_kernel<<<(NCAT * EPAD + T - 1) / T, T>>>(W_iou, W_f, WcatThi, WcatTlo, Ee, EPAD);
    prep_wcat_kernel<<<(NCAT * Hh + T - 1) / T, T>>>(U_iou, U_f, UcatThi, UcatTlo, Hh, Hh);
    gather_x_all_kernel<<<(Ll * Nn * (EPAD / 2) + T - 1) / T, T>>>(
        embed, vocab_ix, token_mask, xhi, xlo);

    const int nu_blocks = (Nn * (Hh / 2) + T - 1) / T;

    int cur = 0;
    for (int l = Ll - 1; l >= 0; --l) {
        const bool leaf = (l == Ll - 1);
        const int prev = cur ^ 1;

        // xw4 = x[l] @ [W_iou | W_f]  (leaf: only the iou column tiles)
        gemm_split_kernel<<<dim3(leaf ? 6 : 8, Nn / 128), 256, GEMM_SMEM>>>(
            xhi + (size_t)l * Nn * EPAD, xlo + (size_t)l * Nn * EPAD,
            WcatThi, WcatTlo, xw4, Nn, EPAD, NCAT);

        if (!leaf) {
            // hu4 = h_prev @ [U_iou | U_f]
            gemm_split_kernel<<<dim3(8, Nn / 128), 256, GEMM_SMEM>>>(
                hhi, hlo, UcatThi, UcatTlo, hu4, Nn, Hh, NCAT);
        }

        float* hf32 = (l == 0) ? out : nullptr;
        if (leaf) {
            node_update_kernel<true><<<nu_blocks, T>>>(
                xw4, nullptr, b_iou, b_f,
                nullptr, nullptr, nullptr, cp[cur], hhi, hlo, hf32);
        } else {
            node_update_kernel<false><<<nu_blocks, T>>>(
                xw4, hu4, b_iou, b_f,
                child_idx + l * Nn * Kk, child_mask + l * Nn * Kk,
                cp[prev], cp[cur], hhi, hlo, hf32);
        }
        cur ^= 1;
    }
}

// round 7
// speedup vs baseline: 6.9257x; 1.1054x over previous
#include <cuda_runtime.h>
#include <cuda_bf16.h>
#include <math.h>
#include <stdint.h>

// Problem constants
#define Vv 50000
#define Ee 300
#define EPAD 320
#define Hh 512
#define Ll 6
#define Nn 8192
#define Kk 4
#define NCAT 2048   // [iou (1536) | f (512)] concatenated output columns

// ---------------------------------------------------------------------------
// Feature gate: tcgen05 exists only on arch-accelerated / family passes.
// ---------------------------------------------------------------------------
#if defined(__CUDA_ARCH__) && (defined(__CUDA_ARCH_FEAT_SM103_ALL) || \
    defined(__CUDA_ARCH_FEAT_SM100_ALL) || defined(__CUDA_ARCH_FEAT_SM110_ALL) || \
    (defined(__CUDA_ARCH_FAMILY_SPECIFIC__) && (__CUDA_ARCH_FAMILY_SPECIFIC__ >= 1000)))
#define USE_TCGEN05 1
#else
#define USE_TCGEN05 0
#endif

// ---------------------------------------------------------------------------
// Scratch
// ---------------------------------------------------------------------------
__device__ __nv_bfloat16 g_xhi[Ll * Nn * EPAD];   // all levels batched
__device__ __nv_bfloat16 g_xlo[Ll * Nn * EPAD];
__device__ __nv_bfloat16 g_hhi[Nn * Hh];
__device__ __nv_bfloat16 g_hlo[Nn * Hh];

__device__ __nv_bfloat16 g_WcatT_hi[NCAT * EPAD];
__device__ __nv_bfloat16 g_WcatT_lo[NCAT * EPAD];
__device__ __nv_bfloat16 g_UcatT_hi[NCAT * Hh];
__device__ __nv_bfloat16 g_UcatT_lo[NCAT * Hh];

__device__ float g_xw4all[(size_t)Ll * Nn * NCAT];  // all-level x @ [W_iou|W_f]
__device__ float g_hu4[Nn * NCAT];                  // h @ [U_iou|U_f]
__device__ float g_cbuf[2 * Nn * Hh];

// ---------------------------------------------------------------------------
// Common PTX helpers
// ---------------------------------------------------------------------------
__device__ __forceinline__ uint32_t smem_u32(const void* p) {
    uint32_t a;
    asm("{ .reg .u64 t; cvta.to.shared.u64 t, %1; cvt.u32.u64 %0, t; }"
        : "=r"(a) : "l"(p));
    return a;
}

__device__ __forceinline__ void cp16(uint32_t dst, const void* src) {
    asm volatile("cp.async.cg.shared.global [%0], [%1], 16;"
                 :: "r"(dst), "l"(src));
}

#define CP_COMMIT()  asm volatile("cp.async.commit_group;" ::: "memory")
#define CP_WAIT0()   asm volatile("cp.async.wait_group 0;" ::: "memory")
#define CP_WAIT1()   asm volatile("cp.async.wait_group 1;" ::: "memory")
#define FENCE_ASYNC() asm volatile("fence.proxy.async.shared::cta;" ::: "memory")
#define MBAR_INIT(a, cnt) \
    asm volatile("mbarrier.init.shared.b64 [%0], %1;" :: "r"(a), "r"(cnt) : "memory")

#define SW128u(o) ((uint32_t)(o) ^ ((((uint32_t)(o)) >> 3) & 0x70u))
#define DESC_BASE ((2ull << 61) | (1ull << 46) | (64ull << 32) | (1ull << 16))
#define MAKE_DESC(a) (DESC_BASE | (((uint64_t)((a) >> 4)) & 0x3FFFull))
// idesc: fp32 accum, bf16 A/B, K-major, M=128, N=256
#define IDESC_N256 (0x10u | 0x80u | 0x400u | (32u << 17) | (8u << 24))

#if USE_TCGEN05
__device__ __forceinline__ uint32_t elect1() {
    uint32_t p;
    asm volatile("{ .reg .pred p; elect.sync _|p, 0xFFFFFFFF; selp.b32 %0,1,0,p; }"
                 : "=r"(p));
    return p;
}

__device__ __forceinline__ void mbar_wait(uint32_t mbar, uint32_t parity) {
    asm volatile(
        "{\n\t.reg .pred P;\n\t"
        "WL_%=:\n\t"
        "mbarrier.try_wait.parity.acquire.cta.shared::cta.b64 P, [%0], %1, 0x989680;\n\t"
        "@P bra.uni WD_%=;\n\t"
        "bra.uni WL_%=;\n\t"
        "WD_%=:\n\t}"
        :: "r"(mbar), "r"(parity) : "memory");
}

// .noinc is load-bearing: the default form pre-increments the pending count
// (net-zero against a pre-counted barrier -> deadlock, as in R6).
#define CPASYNC_MBAR_ARRIVE_NOINC(a) \
    asm volatile("cp.async.mbarrier.arrive.noinc.shared::cta.b64 [%0];" :: "r"(a) : "memory")

#define TC_ALLOC(a, n) \
    asm volatile("tcgen05.alloc.cta_group::1.sync.aligned.shared::cta.b32 [%0], %1;" \
                 :: "r"(a), "r"(n) : "memory")
#define TC_DEALLOC(t, n) \
    asm volatile("tcgen05.dealloc.cta_group::1.sync.aligned.b32 %0, %1;" :: "r"(t), "r"(n))
#define TC_RELINQ() \
    asm volatile("tcgen05.relinquish_alloc_permit.cta_group::1.sync.aligned;")
#define TC_COMMIT(m) \
    asm volatile("tcgen05.commit.cta_group::1.mbarrier::arrive::one.shared::cluster.b64 [%0];" \
                 :: "r"(m) : "memory")
#define TC_FENCE_AFTER()  asm volatile("tcgen05.fence::after_thread_sync;" ::: "memory")
#define TC_FENCE_BEFORE() asm volatile("tcgen05.fence::before_thread_sync;" ::: "memory")
#define TC_WAIT_LD()      asm volatile("tcgen05.wait::ld.sync.aligned;" ::: "memory")

__device__ __forceinline__ void mma_bf16_ss(uint32_t d, uint64_t ad, uint64_t bd,
                                            uint32_t idesc, uint32_t en) {
    asm volatile(
        "{\n\t.reg .pred p;\n\t"
        "setp.ne.u32 p, %4, 0;\n\t"
        "tcgen05.mma.cta_group::1.kind::f16 [%0], %1, %2, %3, {%5,%5,%5,%5}, p;\n\t}"
        :: "r"(d), "l"(ad), "l"(bd), "r"(idesc), "r"(en), "r"(0u) : "memory");
}

__device__ __forceinline__ void ldtm32(uint32_t* r, uint32_t taddr) {
    asm volatile(
        "tcgen05.ld.sync.aligned.32x32b.x32.b32 "
        "{%0, %1, %2, %3, %4, %5, %6, %7, %8, %9, %10, %11, %12, %13, %14, %15, "
        "%16, %17, %18, %19, %20, %21, %22, %23, %24, %25, %26, %27, %28, %29, %30, %31}, [%32];"
        : "=r"(r[0]), "=r"(r[1]), "=r"(r[2]), "=r"(r[3]), "=r"(r[4]), "=r"(r[5]),
          "=r"(r[6]), "=r"(r[7]), "=r"(r[8]), "=r"(r[9]), "=r"(r[10]), "=r"(r[11]),
          "=r"(r[12]), "=r"(r[13]), "=r"(r[14]), "=r"(r[15]), "=r"(r[16]), "=r"(r[17]),
          "=r"(r[18]), "=r"(r[19]), "=r"(r[20]), "=r"(r[21]), "=r"(r[22]), "=r"(r[23]),
          "=r"(r[24]), "=r"(r[25]), "=r"(r[26]), "=r"(r[27]), "=r"(r[28]), "=r"(r[29]),
          "=r"(r[30]), "=r"(r[31])
        : "r"(taddr));
}
#endif  // USE_TCGEN05

// Baseline-ISA warp MMA — fallback body
__device__ __forceinline__ void hmma16816(float* d, const uint32_t* a, const uint32_t* b) {
    asm volatile(
        "mma.sync.aligned.m16n8k16.row.col.f32.bf16.bf16.f32 "
        "{%0,%1,%2,%3}, {%4,%5,%6,%7}, {%8,%9}, {%0,%1,%2,%3};"
        : "+f"(d[0]), "+f"(d[1]), "+f"(d[2]), "+f"(d[3])
        : "r"(a[0]), "r"(a[1]), "r"(a[2]), "r"(a[3]), "r"(b[0]), "r"(b[1]));
}

__device__ __forceinline__ void split_bf16(float v, __nv_bfloat16& hi, __nv_bfloat16& lo) {
    hi = __float2bfloat16(v);
    lo = __float2bfloat16(v - __bfloat162float(hi));
}

// ---------------------------------------------------------------------------
// Weight prep: concatenated transposed split weights.
// ---------------------------------------------------------------------------
__global__ void prep_wcat_kernel(const float* __restrict__ Wa,
                                 const float* __restrict__ Wb,
                                 __nv_bfloat16* __restrict__ Thi,
                                 __nv_bfloat16* __restrict__ Tlo,
                                 int Korig, int Kpad)
{
    int idx = blockIdx.x * blockDim.x + threadIdx.x;
    if (idx >= NCAT * Kpad) return;
    int n = idx / Kpad;
    int k = idx - n * Kpad;
    float v = 0.f;
    if (k < Korig)
        v = (n < 1536) ? Wa[(size_t)k * 1536 + n] : Wb[(size_t)k * 512 + (n - 1536)];
    __nv_bfloat16 hi, lo;
    split_bf16(v, hi, lo);
    Thi[idx] = hi;
    Tlo[idx] = lo;
}

// ---------------------------------------------------------------------------
// Embedding gather + split, ALL levels in one launch
// ---------------------------------------------------------------------------
__global__ void gather_x_all_kernel(const float* __restrict__ embed,
                                    const int* __restrict__ vix,     // [L*N]
                                    const float* __restrict__ tmask, // [L*N]
                                    __nv_bfloat16* __restrict__ xhi,
                                    __nv_bfloat16* __restrict__ xlo)
{
    int idx = blockIdx.x * blockDim.x + threadIdx.x;
    const int QE = EPAD / 2;  // 160
    if (idx >= Ll * Nn * QE) return;
    int n = idx / QE;
    int e = (idx - n * QE) * 2;
    float m = tmask[n];
    float v0 = 0.f, v1 = 0.f;
    if (e < Ee) {
        const float* er = embed + (size_t)vix[n] * Ee + e;
        v0 = er[0] * m;
        v1 = er[1] * m;
    }
    __nv_bfloat16 h0, l0, h1, l1;
    split_bf16(v0, h0, l0);
    split_bf16(v1, h1, l1);
    *(__nv_bfloat162*)(xhi + (size_t)n * EPAD + e) = __nv_bfloat162(h0, h1);
    *(__nv_bfloat162*)(xlo + (size_t)n * EPAD + e) = __nv_bfloat162(l0, l1);
}

// ---------------------------------------------------------------------------
// Split-bf16 GEMM: C[M,Ncol] = (Ahi+Alo)[M,Ks] @ (Bhi+Blo)[Ncol,Ks]^T
// Tile: 128 (M) x 256 (N) per CTA, K-chunks of 64.
// tcgen05 body: mbarrier producer/consumer pipeline, NO bulk syncs in mainloop.
//   warps 4-7 : producers (cp.async -> full[s] via cp.async.mbarrier.arrive.noinc)
//   warp 0 e1 : consumer  (wait full -> 12 MMAs -> commit empty[s] / done)
//   warps 0-3 : epilogue  (wait done -> LDTM -> STG)
// ---------------------------------------------------------------------------
#define STAGE_BYTES 98304   // Ahi 16K | Alo 16K | Bhi 32K | Blo 32K
#define GEMM_SMEM   (2 * STAGE_BYTES + 1024)

__global__ void __launch_bounds__(256)
gemm_split_kernel(const __nv_bfloat16* __restrict__ Ahi,
                  const __nv_bfloat16* __restrict__ Alo,
                  const __nv_bfloat16* __restrict__ Bhi,
                  const __nv_bfloat16* __restrict__ Blo,
                  float* __restrict__ C,
                  int M, int Ks, int Ncol)
{
#if USE_TCGEN05
    extern __shared__ char smem_raw[];
    const uint32_t sb = smem_u32(smem_raw);
    const uint32_t ctrl = sb;   // [0] tmem ptr; mbars: full@16,24  empty@32,40  done@48
    const uint32_t tiles = (sb + 64 + 1023) & ~1023u;

    const int tid = threadIdx.x;
    const int wid = tid >> 5;
    const int lid = tid & 31;
    const int m0 = blockIdx.y * 128;
    const int n0 = blockIdx.x * 256;
    const int NC = Ks >> 6;

    if (wid == 0) TC_ALLOC(ctrl, 256);
    if (tid == 0) {
        MBAR_INIT(ctrl + 16, 128);  // full[0]  (128 producer threads)
        MBAR_INIT(ctrl + 24, 128);  // full[1]
        MBAR_INIT(ctrl + 32, 1);    // empty[0] (consumer commit)
        MBAR_INIT(ctrl + 40, 1);    // empty[1]
        MBAR_INIT(ctrl + 48, 1);    // done
    }
    __syncthreads();
    uint32_t tmem;
    asm("ld.shared.b32 %0, [%1];" : "=r"(tmem) : "r"(ctrl));

    if (wid >= 4) {
        // ------------------- producers (128 threads) -------------------
        const int p = tid - 128;
        for (int c = 0; c < NC; c++) {
            const int s = c & 1;
            const uint32_t ph = 1u ^ ((uint32_t)(c >> 1) & 1u);
            mbar_wait(ctrl + 32 + s * 8, ph);   // fresh-barrier pass on first use
            const uint32_t tb = tiles + s * STAGE_BYTES;
            const int k0 = c * 64;
#pragma unroll
            for (int q = p; q < 1024; q += 128) {          // A: 128 rows x 8 cols
                int row = q >> 3;
                int cc = q & 7;
                uint32_t soff = SW128u(row * 128 + cc * 16);
                size_t ao = (size_t)(m0 + row) * Ks + k0 + cc * 8;
                cp16(tb + soff,         Ahi + ao);
                cp16(tb + 16384 + soff, Alo + ao);
            }
#pragma unroll
            for (int q = p; q < 2048; q += 128) {          // B: 256 rows x 8 cols
                int row = q >> 3;
                int cc = q & 7;
                uint32_t soff = SW128u(row * 128 + cc * 16);
                size_t bo = (size_t)(n0 + row) * Ks + k0 + cc * 8;
                cp16(tb + 32768 + soff, Bhi + bo);
                cp16(tb + 65536 + soff, Blo + bo);
            }
            CPASYNC_MBAR_ARRIVE_NOINC(ctrl + 16 + s * 8);
        }
    } else if (wid == 0 && elect1()) {
        // ------------------- consumer (1 thread) -------------------
        for (int c = 0; c < NC; c++) {
            const int s = c & 1;
            const uint32_t ph = (uint32_t)(c >> 1) & 1u;
            mbar_wait(ctrl + 16 + s * 8, ph);
            FENCE_ASYNC();
            const uint32_t tb = tiles + s * STAGE_BYTES;
            uint64_t dah = MAKE_DESC(tb);
            uint64_t dal = MAKE_DESC(tb + 16384);
            uint64_t dbh = MAKE_DESC(tb + 32768);
            uint64_t dbl = MAKE_DESC(tb + 65536);
#pragma unroll
            for (int ks = 0; ks < 4; ks++)
                mma_bf16_ss(tmem, dah + 2 * ks, dbh + 2 * ks, IDESC_N256,
                            (c == 0 && ks == 0) ? 0u : 1u);
#pragma unroll
            for (int ks = 0; ks < 4; ks++)
                mma_bf16_ss(tmem, dah + 2 * ks, dbl + 2 * ks, IDESC_N256, 1u);
#pragma unroll
            for (int ks = 0; ks < 4; ks++)
                mma_bf16_ss(tmem, dal + 2 * ks, dbh + 2 * ks, IDESC_N256, 1u);
            // last chunk's commit gates the epilogue; earlier ones recycle stage
            TC_COMMIT((c == NC - 1) ? (ctrl + 48) : (ctrl + 32 + s * 8));
        }
    }

    // ------------------- epilogue (warps 0-3) -------------------
    if (wid < 4) {
        mbar_wait(ctrl + 48, 0);
        TC_FENCE_AFTER();
        float* crow = C + (size_t)(m0 + wid * 32 + lid) * Ncol + n0;
#pragma unroll
        for (int b = 0; b < 8; b++) {
            uint32_t r[32];
            ldtm32(r, tmem + b * 32);
            TC_WAIT_LD();
#pragma unroll
            for (int j = 0; j < 32; j += 4) {
                float4 v;
                v.x = __uint_as_float(r[j + 0]);
                v.y = __uint_as_float(r[j + 1]);
                v.z = __uint_as_float(r[j + 2]);
                v.w = __uint_as_float(r[j + 3]);
                *(float4*)(crow + b * 32 + j) = v;
            }
        }
        TC_FENCE_BEFORE();
    }

    __syncthreads();
    if (wid == 0) {
        TC_RELINQ();
        TC_DEALLOC(tmem, 256);
    }

#else  // ------------------------- mma.sync fallback -------------------------
    extern __shared__ char smem_raw[];
    const int tid = threadIdx.x;
    const int wid = tid >> 5;
    const int lane = tid & 31;
    const int wm = wid >> 1;
    const int wn = wid & 1;
    const int r4 = lane >> 2;
    const int tig = lane & 3;
    const int m0 = blockIdx.y * 128;
    const int NC = Ks >> 5;

    for (int half = 0; half < 2; half++) {
        const int n0 = blockIdx.x * 256 + half * 128;

        float acc[2][8][4];
#pragma unroll
        for (int i = 0; i < 2; i++)
#pragma unroll
            for (int j = 0; j < 8; j++)
#pragma unroll
                for (int v = 0; v < 4; v++) acc[i][j][v] = 0.f;

        auto ldtile = [&](int buf, int k0) {
            uint32_t tb = smem_u32(smem_raw) + buf * 40960;
#pragma unroll
            for (int q = tid; q < 512; q += 256) {
                int row = q >> 2;
                int c = q & 3;
                uint32_t d = tb + row * 80 + c * 16;
                size_t ao = (size_t)(m0 + row) * Ks + k0 + c * 8;
                size_t bo = (size_t)(n0 + row) * Ks + k0 + c * 8;
                cp16(d,         Ahi + ao);
                cp16(d + 10240, Alo + ao);
                cp16(d + 20480, Bhi + bo);
                cp16(d + 30720, Blo + bo);
            }
            CP_COMMIT();
        };

        ldtile(0, 0);

        for (int c = 0; c < NC; c++) {
            const int cur = c & 1;
            if (c + 1 < NC) {
                ldtile(cur ^ 1, (c + 1) * 32);
                CP_WAIT1();
            } else {
                CP_WAIT0();
            }
            __syncthreads();

            const char* tb = smem_raw + cur * 40960;
#pragma unroll
            for (int kk = 0; kk < 32; kk += 16) {
                uint32_t ahi[2][4], alo[2][4], bhi[8][2], blo[8][2];
#pragma unroll
                for (int mi = 0; mi < 2; mi++) {
                    int row = wm * 32 + mi * 16 + r4;
                    int cb = (kk + tig * 2) * 2;
                    ahi[mi][0] = *(const uint32_t*)(tb + row * 80 + cb);
                    ahi[mi][1] = *(const uint32_t*)(tb + (row + 8) * 80 + cb);
                    ahi[mi][2] = *(const uint32_t*)(tb + row * 80 + cb + 16);
                    ahi[mi][3] = *(const uint32_t*)(tb + (row + 8) * 80 + cb + 16);
                    alo[mi][0] = *(const uint32_t*)(tb + 10240 + row * 80 + cb);
                    alo[mi][1] = *(const uint32_t*)(tb + 10240 + (row + 8) * 80 + cb);
                    alo[mi][2] = *(const uint32_t*)(tb + 10240 + row * 80 + cb + 16);
                    alo[mi][3] = *(const uint32_t*)(tb + 10240 + (row + 8) * 80 + cb + 16);
                }
#pragma unroll
                for (int ni = 0; ni < 8; ni++) {
                    int nr = wn * 64 + ni * 8 + r4;
                    int cb = (kk + tig * 2) * 2;
                    bhi[ni][0] = *(const uint32_t*)(tb + 20480 + nr * 80 + cb);
                    bhi[ni][1] = *(const uint32_t*)(tb + 20480 + nr * 80 + cb + 16);
                    blo[ni][0] = *(const uint32_t*)(tb + 30720 + nr * 80 + cb);
                    blo[ni][1] = *(const uint32_t*)(tb + 30720 + nr * 80 + cb + 16);
                }
#pragma unroll
                for (int mi = 0; mi < 2; mi++)
#pragma unroll
                    for (int ni = 0; ni < 8; ni++) {
                        hmma16816(acc[mi][ni], ahi[mi], bhi[ni]);
                        hmma16816(acc[mi][ni], ahi[mi], blo[ni]);
                        hmma16816(acc[mi][ni], alo[mi], bhi[ni]);
                    }
            }
            __syncthreads();
        }

#pragma unroll
        for (int mi = 0; mi < 2; mi++)
#pragma unroll
            for (int ni = 0; ni < 8; ni++) {
                int row = m0 + wm * 32 + mi * 16 + r4;
                int col = n0 + wn * 64 + ni * 8 + tig * 2;
                *(float2*)(C + (size_t)row * Ncol + col) =
                    make_float2(acc[mi][ni][0], acc[mi][ni][1]);
                *(float2*)(C + (size_t)(row + 8) * Ncol + col) =
                    make_float2(acc[mi][ni][2], acc[mi][ni][3]);
            }
        __syncthreads();
    }
#endif
}

// ---------------------------------------------------------------------------
// Node update (fused gates + output-side child gathers + h split)
// ---------------------------------------------------------------------------
__device__ __forceinline__ float sigmoidf_(float v) {
    return 1.f / (1.f + __expf(-v));
}

template <bool LEAF>
__global__ void node_update_kernel(const float* __restrict__ xw4,
                                   const float* __restrict__ hu4,
                                   const float* __restrict__ b_iou,
                                   const float* __restrict__ b_f,
                                   const int* __restrict__ cidx,
                                   const float* __restrict__ cmask,
                                   const float* __restrict__ c_prev,
                                   float* __restrict__ c_out,
                                   __nv_bfloat16* __restrict__ hhi,
                                   __nv_bfloat16* __restrict__ hlo,
                                   float* __restrict__ h_f32)   // may be null
{
    int idx = blockIdx.x * blockDim.x + threadIdx.x;   // over Nn * Hh/2
    if (idx >= Nn * (Hh / 2)) return;
    int n = idx >> 8;              // / 256
    int j = (idx & 255) * 2;

    const float* xw = xw4 + (size_t)n * NCAT;
    float2 gi = *(const float2*)(xw + j);
    float2 go = *(const float2*)(xw + 512 + j);
    float2 gu = *(const float2*)(xw + 1024 + j);
    {
        float2 b0 = *(const float2*)(b_iou + j);
        float2 b1 = *(const float2*)(b_iou + 512 + j);
        float2 b2 = *(const float2*)(b_iou + 1024 + j);
        gi.x += b0.x; gi.y += b0.y;
        go.x += b1.x; go.y += b1.y;
        gu.x += b2.x; gu.y += b2.y;
    }

    float fcx = 0.f, fcy = 0.f;
    if (!LEAF) {
        float2 bf = *(const float2*)(b_f + j);
        float2 xf = *(const float2*)(xw + 1536 + j);
        xf.x += bf.x; xf.y += bf.y;
#pragma unroll
        for (int k = 0; k < Kk; k++) {
            int ci = cidx[n * Kk + k];
            float m = cmask[n * Kk + k];
            const float* hr = hu4 + (size_t)ci * NCAT;
            float2 hi_ = *(const float2*)(hr + j);
            float2 ho_ = *(const float2*)(hr + 512 + j);
            float2 hu_ = *(const float2*)(hr + 1024 + j);
            float2 hf_ = *(const float2*)(hr + 1536 + j);
            gi.x += m * hi_.x; gi.y += m * hi_.y;
            go.x += m * ho_.x; go.y += m * ho_.y;
            gu.x += m * hu_.x; gu.y += m * hu_.y;
            float fx = sigmoidf_(xf.x + m * hf_.x);
            float fy = sigmoidf_(xf.y + m * hf_.y);
            float2 cpv = *(const float2*)(c_prev + (size_t)ci * Hh + j);
            fcx += fx * cpv.x * m;
            fcy += fy * cpv.y * m;
        }
    }

    float cx = sigmoidf_(gi.x) * tanhf(gu.x) + fcx;
    float cy = sigmoidf_(gi.y) * tanhf(gu.y) + fcy;
    *(float2*)(c_out + (size_t)n * Hh + j) = make_float2(cx, cy);

    float hx = sigmoidf_(go.x) * tanhf(cx);
    float hy = sigmoidf_(go.y) * tanhf(cy);

    __nv_bfloat16 h0, l0, h1, l1;
    split_bf16(hx, h0, l0);
    split_bf16(hy, h1, l1);
    *(__nv_bfloat162*)(hhi + (size_t)n * Hh + j) = __nv_bfloat162(h0, h1);
    *(__nv_bfloat162*)(hlo + (size_t)n * Hh + j) = __nv_bfloat162(l0, l1);
    if (h_f32)
        *(float2*)(h_f32 + (size_t)n * Hh + j) = make_float2(hx, hy);
}

// ---------------------------------------------------------------------------
// Launch
// ---------------------------------------------------------------------------
extern "C" void kernel_launch(void* const* d_in, const int* in_sizes, int n_in,
                              void* d_out, int out_size)
{
    const int*   vocab_ix   = (const int*)d_in[0];
    const int*   child_idx  = (const int*)d_in[1];
    const float* token_mask = (const float*)d_in[2];
    const float* child_mask = (const float*)d_in[3];
    const float* embed      = (const float*)d_in[4];
    const float* W_iou      = (const float*)d_in[5];   // [E, 3H]
    const float* U_iou      = (const float*)d_in[6];   // [H, 3H]
    const float* b_iou      = (const float*)d_in[7];
    const float* W_f        = (const float*)d_in[8];   // [E, H]
    const float* U_f        = (const float*)d_in[9];   // [H, H]
    const float* b_f        = (const float*)d_in[10];
    float* out = (float*)d_out;

    cudaFuncSetAttribute(gemm_split_kernel,
                         cudaFuncAttributeMaxDynamicSharedMemorySize, GEMM_SMEM);

    __nv_bfloat16 *xhi, *xlo, *hhi, *hlo;
    __nv_bfloat16 *WcatThi, *WcatTlo, *UcatThi, *UcatTlo;
    float *xw4all, *hu4, *cbuf;
    cudaGetSymbolAddress((void**)&xhi, g_xhi);
    cudaGetSymbolAddress((void**)&xlo, g_xlo);
    cudaGetSymbolAddress((void**)&hhi, g_hhi);
    cudaGetSymbolAddress((void**)&hlo, g_hlo);
    cudaGetSymbolAddress((void**)&WcatThi, g_WcatT_hi);
    cudaGetSymbolAddress((void**)&WcatTlo, g_WcatT_lo);
    cudaGetSymbolAddress((void**)&UcatThi, g_UcatT_hi);
    cudaGetSymbolAddress((void**)&UcatTlo, g_UcatT_lo);
    cudaGetSymbolAddress((void**)&xw4all, g_xw4all);
    cudaGetSymbolAddress((void**)&hu4, g_hu4);
    cudaGetSymbolAddress((void**)&cbuf, g_cbuf);

    float* cp[2] = { cbuf, cbuf + (size_t)Nn * Hh };

    const int T = 256;

    // Weight prep + all-level x gather + ALL xw4 GEMMs up front
    prep_wcat_kernel<<<(NCAT * EPAD + T - 1) / T, T>>>(W_iou, W_f, WcatThi, WcatTlo, Ee, EPAD);
    prep_wcat_kernel<<<(NCAT * Hh + T - 1) / T, T>>>(U_iou, U_f, UcatThi, UcatTlo, Hh, Hh);
    gather_x_all_kernel<<<(Ll * Nn * (EPAD / 2) + T - 1) / T, T>>>(
        embed, vocab_ix, token_mask, xhi, xlo);

    // xw4all = x(all levels) @ [W_iou | W_f]   M = 49152
    gemm_split_kernel<<<dim3(8, Ll * Nn / 128), 256, GEMM_SMEM>>>(
        xhi, xlo, WcatThi, WcatTlo, xw4all, Ll * Nn, EPAD, NCAT);

    const int nu_blocks = (Nn * (Hh / 2) + T - 1) / T;

    int cur = 0;
    for (int l = Ll - 1; l >= 0; --l) {
        const bool leaf = (l == Ll - 1);
        const int prev = cur ^ 1;

        if (!leaf) {
            // hu4 = h_prev @ [U_iou | U_f]
            gemm_split_kernel<<<dim3(8, Nn / 128), 256, GEMM_SMEM>>>(
                hhi, hlo, UcatThi, UcatTlo, hu4, Nn, Hh, NCAT);
        }

        const float* xw4l = xw4all + (size_t)l * Nn * NCAT;
        float* hf32 = (l == 0) ? out : nullptr;
        if (leaf) {
            node_update_kernel<true><<<nu_blocks, T>>>(
                xw4l, nullptr, b_iou, b_f,
                nullptr, nullptr, nullptr, cp[cur], hhi, hlo, hf32);
        } else {
            node_update_kernel<false><<<nu_blocks, T>>>(
                xw4l, hu4, b_iou, b_f,
                child_idx + l * Nn * Kk, child_mask + l * Nn * Kk,
                cp[prev], cp[cur], hhi, hlo, hf32);
        }
        cur ^= 1;
    }
}